// round 2
// baseline (speedup 1.0000x reference)
#include <cuda_runtime.h>
#include <math.h>

#define BB 4
#define TT 1024
#define DD 1024
#define HH 16
#define HD 64

// ---------------- scratch (device globals; no allocation allowed) ----------
__device__ float g_QQ[BB*TT*2*DD];     // x_q @ Wq          (B,T,2048)
__device__ float g_KV[BB*TT*3*DD];     // x_kv @ Wkv        (B,T,3072)
__device__ float g_q1[BB*HH*TT*HD];    // (B,H,T,64) rmsnormed
__device__ float g_q2[BB*HH*TT*HD];
__device__ float g_k1[BB*HH*TT*HD];
__device__ float g_k2[BB*HH*TT*HD];
__device__ float g_v [BB*HH*TT*HD];
__device__ float g_y [BB*HH*TT*HD];    // attention output (B,H,T,64)
__device__ float g_yt[BB*TT*DD];       // groupnormed, (B,T,D)

// ---------------- fp32 tiled GEMM: C[M,N] = A[M,K] @ B[K,N] ----------------
// BM=BN=128, BK=16, 256 threads, 8x8 microtile.
__global__ __launch_bounds__(256, 2)
void sgemm(const float* __restrict__ A, const float* __restrict__ B,
           float* __restrict__ C, int M, int N, int K)
{
    __shared__ float As[16][128];   // transposed: As[k][m]
    __shared__ float Bs[16][128];   // Bs[k][n]

    const int tid = threadIdx.x;
    const int bx = blockIdx.x;      // N tiles
    const int by = blockIdx.y;      // M tiles

    const int ar = tid >> 2;            // 0..63
    const int ac = (tid & 3) << 2;      // 0,4,8,12
    const int br = tid >> 5;            // 0..7
    const int bc = (tid & 31) << 2;     // 0..124
    const int ty = tid >> 4;            // 0..15
    const int tx = tid & 15;            // 0..15

    const float* Ab = A + (size_t)(by * 128) * K;
    const float* Bb = B + bx * 128;

    float acc[8][8];
#pragma unroll
    for (int i = 0; i < 8; i++)
#pragma unroll
        for (int j = 0; j < 8; j++) acc[i][j] = 0.f;

    for (int k0 = 0; k0 < K; k0 += 16) {
        float4 a0 = *(const float4*)(Ab + (size_t)ar * K + k0 + ac);
        float4 a1 = *(const float4*)(Ab + (size_t)(ar + 64) * K + k0 + ac);
        As[ac + 0][ar] = a0.x; As[ac + 1][ar] = a0.y;
        As[ac + 2][ar] = a0.z; As[ac + 3][ar] = a0.w;
        As[ac + 0][ar + 64] = a1.x; As[ac + 1][ar + 64] = a1.y;
        As[ac + 2][ar + 64] = a1.z; As[ac + 3][ar + 64] = a1.w;
        float4 b0 = *(const float4*)(Bb + (size_t)(k0 + br) * N + bc);
        float4 b1 = *(const float4*)(Bb + (size_t)(k0 + br + 8) * N + bc);
        *(float4*)&Bs[br][bc]     = b0;
        *(float4*)&Bs[br + 8][bc] = b1;
        __syncthreads();

#pragma unroll
        for (int kk = 0; kk < 16; kk++) {
            float a[8], b[8];
            *(float4*)(a)     = *(const float4*)&As[kk][ty * 8];
            *(float4*)(a + 4) = *(const float4*)&As[kk][ty * 8 + 4];
            *(float4*)(b)     = *(const float4*)&Bs[kk][tx * 8];
            *(float4*)(b + 4) = *(const float4*)&Bs[kk][tx * 8 + 4];
#pragma unroll
            for (int i = 0; i < 8; i++)
#pragma unroll
                for (int j = 0; j < 8; j++)
                    acc[i][j] = fmaf(a[i], b[j], acc[i][j]);
        }
        __syncthreads();
    }

    float* Cb = C + (size_t)(by * 128 + ty * 8) * N + bx * 128 + tx * 8;
#pragma unroll
    for (int i = 0; i < 8; i++) {
        float4 o0, o1;
        o0.x = acc[i][0]; o0.y = acc[i][1]; o0.z = acc[i][2]; o0.w = acc[i][3];
        o1.x = acc[i][4]; o1.y = acc[i][5]; o1.z = acc[i][6]; o1.w = acc[i][7];
        *(float4*)(Cb + (size_t)i * N)     = o0;
        *(float4*)(Cb + (size_t)i * N + 4) = o1;
    }
}

// ---------------- RMSNorm for q1/q2: QQ(B,T,2048) -> g_q1/g_q2 (B,H,T,64) --
__global__ void rms_q(const float* __restrict__ qn1, const float* __restrict__ qn2)
{
    int item = blockIdx.x * 8 + (threadIdx.x >> 5);   // ((b*T+t)*H + h)*2 + half
    int lane = threadIdx.x & 31;
    int half = item & 1;
    int h = (item >> 1) & (HH - 1);
    int t = (item >> 5) & (TT - 1);
    int b = item >> 15;
    const float* src = g_QQ + (size_t)(b * TT + t) * 2048 + half * 1024 + h * 64;
    float v0 = src[lane], v1 = src[lane + 32];
    float ss = v0 * v0 + v1 * v1;
    ss += __shfl_xor_sync(0xffffffffu, ss, 16);
    ss += __shfl_xor_sync(0xffffffffu, ss, 8);
    ss += __shfl_xor_sync(0xffffffffu, ss, 4);
    ss += __shfl_xor_sync(0xffffffffu, ss, 2);
    ss += __shfl_xor_sync(0xffffffffu, ss, 1);
    float inv = rsqrtf(ss * (1.0f / 64.0f) + 1e-5f);
    const float* w = half ? qn2 : qn1;
    float* dst = (half ? g_q2 : g_q1) + (size_t)((b * HH + h) * TT + t) * 64;
    dst[lane]      = v0 * inv * w[lane];
    dst[lane + 32] = v1 * inv * w[lane + 32];
}

// ------- RMSNorm for k1/k2 + copy v: KV(B,T,3072) -> g_k1/g_k2/g_v --------
__global__ void rms_kv(const float* __restrict__ kn1, const float* __restrict__ kn2)
{
    int item = blockIdx.x * 8 + (threadIdx.x >> 5);   // ((b*T+t)*H + h)*3 + part
    int lane = threadIdx.x & 31;
    int part = item % 3;
    int rest = item / 3;
    int h = rest & (HH - 1);
    int t = (rest >> 4) & (TT - 1);
    int b = rest >> 14;
    const float* src = g_KV + (size_t)(b * TT + t) * 3072 + part * 1024 + h * 64;
    float v0 = src[lane], v1 = src[lane + 32];
    size_t doff = (size_t)((b * HH + h) * TT + t) * 64;
    if (part == 2) {
        g_v[doff + lane] = v0;
        g_v[doff + lane + 32] = v1;
        return;
    }
    float ss = v0 * v0 + v1 * v1;
    ss += __shfl_xor_sync(0xffffffffu, ss, 16);
    ss += __shfl_xor_sync(0xffffffffu, ss, 8);
    ss += __shfl_xor_sync(0xffffffffu, ss, 4);
    ss += __shfl_xor_sync(0xffffffffu, ss, 2);
    ss += __shfl_xor_sync(0xffffffffu, ss, 1);
    float inv = rsqrtf(ss * (1.0f / 64.0f) + 1e-5f);
    const float* w = part ? kn2 : kn1;
    float* dst = (part ? g_k2 : g_k1) + doff;
    dst[lane]      = v0 * inv * w[lane];
    dst[lane + 32] = v1 * inv * w[lane + 32];
}

// ---------------- flash attention (two branches, shared V) -----------------
#define PS 68                           // padded smem row stride (floats)
#define ATTN_SMEM (6 * 64 * PS * 4)     // 104448 bytes

__device__ __forceinline__ void attn_branch(
    const float* __restrict__ qs, const float* __restrict__ ks,
    const float* __restrict__ vsm, float* __restrict__ Psm,
    int r, int cg, float& m, float& l, float* acc)
{
    // ---- S = Q K^T for 16 columns owned by this thread ----
    float s[16];
#pragma unroll
    for (int c = 0; c < 16; c++) s[c] = 0.f;
    const float* qrow = qs + r * PS;
    const float* kb = ks + (cg * 16) * PS;
    for (int d = 0; d < 64; d += 4) {
        float4 qv = *(const float4*)(qrow + d);
#pragma unroll
        for (int c = 0; c < 16; c++) {
            float4 kv = *(const float4*)(kb + c * PS + d);
            s[c] = fmaf(qv.x, kv.x, s[c]);
            s[c] = fmaf(qv.y, kv.y, s[c]);
            s[c] = fmaf(qv.z, kv.z, s[c]);
            s[c] = fmaf(qv.w, kv.w, s[c]);
        }
    }
    // ---- online softmax update (per-row, quad-replicated) ----
    float mloc = -1e30f;
#pragma unroll
    for (int c = 0; c < 16; c++) { s[c] *= 0.125f; mloc = fmaxf(mloc, s[c]); }
    mloc = fmaxf(mloc, __shfl_xor_sync(0xffffffffu, mloc, 1));
    mloc = fmaxf(mloc, __shfl_xor_sync(0xffffffffu, mloc, 2));
    float mnew = fmaxf(m, mloc);
    float alpha = __expf(m - mnew);
    float lloc = 0.f;
#pragma unroll
    for (int c = 0; c < 16; c++) { s[c] = __expf(s[c] - mnew); lloc += s[c]; }
    lloc += __shfl_xor_sync(0xffffffffu, lloc, 1);
    lloc += __shfl_xor_sync(0xffffffffu, lloc, 2);
    l = l * alpha + lloc;
    m = mnew;
    float* pr = Psm + r * PS + cg * 16;
#pragma unroll
    for (int c = 0; c < 16; c++) pr[c] = s[c];
    __syncthreads();
    // ---- PV: acc over this thread's 16 dims (cg reinterpreted as dim group)
#pragma unroll
    for (int i = 0; i < 16; i++) acc[i] *= alpha;
    const float* prow = Psm + r * PS;
    const float* vb = vsm + cg * 16;
#pragma unroll 4
    for (int c = 0; c < 64; c++) {
        float p = prow[c];
#pragma unroll
        for (int i = 0; i < 16; i += 4) {
            float4 vv = *(const float4*)(vb + c * PS + i);
            acc[i + 0] = fmaf(p, vv.x, acc[i + 0]);
            acc[i + 1] = fmaf(p, vv.y, acc[i + 1]);
            acc[i + 2] = fmaf(p, vv.z, acc[i + 2]);
            acc[i + 3] = fmaf(p, vv.w, acc[i + 3]);
        }
    }
    __syncthreads();   // protect Psm/vsm before reuse
}

__global__ __launch_bounds__(256, 2)
void attn_kernel(const float* __restrict__ lmb)
{
    extern __shared__ float sm[];
    float* q1s = sm;
    float* q2s = sm + 1 * 64 * PS;
    float* k1s = sm + 2 * 64 * PS;
    float* k2s = sm + 3 * 64 * PS;
    float* vsm = sm + 4 * 64 * PS;
    float* Psm = sm + 5 * 64 * PS;

    const int tid = threadIdx.x;
    const int qt = blockIdx.x, h = blockIdx.y, b = blockIdx.z;
    const size_t bh = (size_t)(b * HH + h) * (TT * HD);

    {   // load Q tiles (64 rows x 64)
        size_t qbase = bh + (size_t)qt * 64 * 64;
        for (int i = tid; i < 1024; i += 256) {
            int row = i >> 4; int c4 = (i & 15) << 2;
            *(float4*)(q1s + row * PS + c4) = *(const float4*)(g_q1 + qbase + row * 64 + c4);
            *(float4*)(q2s + row * PS + c4) = *(const float4*)(g_q2 + qbase + row * 64 + c4);
        }
    }

    const int r = tid >> 2;
    const int cg = tid & 3;
    float m1 = -1e30f, l1 = 0.f, m2 = -1e30f, l2 = 0.f;
    float acc1[16], acc2[16];
#pragma unroll
    for (int i = 0; i < 16; i++) { acc1[i] = 0.f; acc2[i] = 0.f; }

    for (int kt = 0; kt < 16; kt++) {
        __syncthreads();
        size_t kbase = bh + (size_t)kt * 64 * 64;
        for (int i = tid; i < 1024; i += 256) {
            int row = i >> 4; int c4 = (i & 15) << 2;
            *(float4*)(k1s + row * PS + c4) = *(const float4*)(g_k1 + kbase + row * 64 + c4);
            *(float4*)(k2s + row * PS + c4) = *(const float4*)(g_k2 + kbase + row * 64 + c4);
            *(float4*)(vsm + row * PS + c4) = *(const float4*)(g_v  + kbase + row * 64 + c4);
        }
        __syncthreads();
        attn_branch(q1s, k1s, vsm, Psm, r, cg, m1, l1, acc1);
        attn_branch(q2s, k2s, vsm, Psm, r, cg, m2, l2, acc2);
    }

    float cH = log1pf(__expf(lmb[h]));
    float inv1 = 1.f / l1, inv2 = 1.f / l2;
    size_t obase = bh + (size_t)(qt * 64 + r) * 64 + cg * 16;
#pragma unroll
    for (int i = 0; i < 16; i += 4) {
        float4 o;
        o.x = acc1[i + 0] * inv1 - cH * acc2[i + 0] * inv2;
        o.y = acc1[i + 1] * inv1 - cH * acc2[i + 1] * inv2;
        o.z = acc1[i + 2] * inv1 - cH * acc2[i + 2] * inv2;
        o.w = acc1[i + 3] * inv1 - cH * acc2[i + 3] * inv2;
        *(float4*)(g_y + obase + i) = o;
    }
}

// ---------------- GroupNorm per (b,h) over (T, HD), then relayout ----------
__global__ void groupnorm_kernel(const float* __restrict__ gn_w,
                                 const float* __restrict__ gn_b)
{
    __shared__ float rs[256], rq[256];
    const int bh = blockIdx.x;                 // b*16 + h
    const float* src = g_y + (size_t)bh * TT * HD;
    const int tid = threadIdx.x;
    float s = 0.f, sq = 0.f;
    for (int i = tid; i < TT * HD; i += 256) {
        float v = src[i]; s += v; sq += v * v;
    }
    rs[tid] = s; rq[tid] = sq;
    __syncthreads();
    for (int off = 128; off > 0; off >>= 1) {
        if (tid < off) { rs[tid] += rs[tid + off]; rq[tid] += rq[tid + off]; }
        __syncthreads();
    }
    float mu  = rs[0] * (1.f / 65536.f);
    float var = rq[0] * (1.f / 65536.f) - mu * mu;
    float inv = rsqrtf(var + 1e-5f);
    int b = bh >> 4, h = bh & 15;
    for (int i = tid; i < TT * HD; i += 256) {
        int t = i >> 6, d = i & 63;
        float v = (src[i] - mu) * inv;
        g_yt[(size_t)(b * TT + t) * DD + h * 64 + d] =
            v * gn_w[h * 64 + d] + gn_b[h * 64 + d];
    }
}

// ---------------------------------------------------------------------------
extern "C" void kernel_launch(void* const* d_in, const int* in_sizes, int n_in,
                              void* d_out, int out_size)
{
    const float* x_q  = (const float*)d_in[0];
    const float* x_kv = (const float*)d_in[1];
    const float* Wq   = (const float*)d_in[2];
    const float* Wkv  = (const float*)d_in[3];
    const float* Wc   = (const float*)d_in[4];
    const float* qn1  = (const float*)d_in[5];
    const float* kn1  = (const float*)d_in[6];
    const float* qn2  = (const float*)d_in[7];
    const float* kn2  = (const float*)d_in[8];
    const float* gn_w = (const float*)d_in[9];
    const float* gn_b = (const float*)d_in[10];
    const float* lmb  = (const float*)d_in[11];
    float* out = (float*)d_out;
    (void)in_sizes; (void)n_in; (void)out_size;

    float *QQ, *KV, *YT;
    cudaGetSymbolAddress((void**)&QQ, g_QQ);
    cudaGetSymbolAddress((void**)&KV, g_KV);
    cudaGetSymbolAddress((void**)&YT, g_yt);

    cudaFuncSetAttribute(attn_kernel,
        cudaFuncAttributeMaxDynamicSharedMemorySize, ATTN_SMEM);

    // 1) projections
    sgemm<<<dim3(2048 / 128, 4096 / 128), 256>>>(x_q,  Wq,  QQ, 4096, 2048, 1024);
    sgemm<<<dim3(3072 / 128, 4096 / 128), 256>>>(x_kv, Wkv, KV, 4096, 3072, 1024);
    // 2) per-head RMSNorm + head-major relayout
    rms_q <<<16384, 256>>>(qn1, qn2);
    rms_kv<<<24576, 256>>>(kn1, kn2);
    // 3) differential flash attention
    attn_kernel<<<dim3(16, 16, 4), 256, ATTN_SMEM>>>(lmb);
    // 4) GroupNorm + relayout to (B,T,D)
    groupnorm_kernel<<<64, 256>>>(gn_w, gn_b);
    // 5) output projection
    sgemm<<<dim3(1024 / 128, 4096 / 128), 256>>>(YT, Wc, out, 4096, 1024, 1024);
}

// round 3
// speedup vs baseline: 3.0003x; 3.0003x over previous
#include <cuda_runtime.h>
#include <math.h>

#define BB 4
#define TT 1024
#define DD 1024
#define HH 16
#define HD 64

typedef unsigned long long ull;

// ---- packed f32x2 helpers (SASS FFMA2 path; ptxas never emits from C++) ----
#define FMA2(d,a,b,c) asm("fma.rn.f32x2 %0, %1, %2, %3;" : "=l"(d) : "l"(a), "l"(b), "l"(c))
#define MUL2(d,a,b)   asm("mul.rn.f32x2 %0, %1, %2;"     : "=l"(d) : "l"(a), "l"(b))
#define PK2(d,lo,hi)  asm("mov.b64 %0, {%1, %2};" : "=l"(d) : "f"(lo), "f"(hi))
#define UPK2(lo,hi,s) asm("mov.b64 {%0, %1}, %2;" : "=f"(lo), "=f"(hi) : "l"(s))

// ---------------- scratch (device globals; no allocation allowed) ----------
__device__ float g_QQ[BB*TT*2*DD];     // x_q @ Wq          (B,T,2048)
__device__ float g_KV[BB*TT*3*DD];     // x_kv @ Wkv        (B,T,3072)
__device__ float g_q1[BB*HH*TT*HD];    // (B,H,T,64) rmsnormed
__device__ float g_q2[BB*HH*TT*HD];
__device__ float g_k1[BB*HH*TT*HD];
__device__ float g_k2[BB*HH*TT*HD];
__device__ float g_v [BB*HH*TT*HD];
__device__ float g_y [BB*HH*TT*HD];    // attention output (B,H,T,64)
__device__ float g_yt[BB*TT*DD];       // groupnormed, (B,T,D)

// ---------------- fp32 tiled GEMM, FFMA2 inner: C = A @ B ------------------
// BM=BN=128, BK=16, 256 threads, 8x8 microtile (as 8x4 f32x2 pairs).
__global__ __launch_bounds__(256, 2)
void sgemm(const float* __restrict__ A, const float* __restrict__ B,
           float* __restrict__ C, int M, int N, int K)
{
    __shared__ float As[16][128];   // transposed: As[k][m]
    __shared__ float Bs[16][128];   // Bs[k][n]

    const int tid = threadIdx.x;
    const int bx = blockIdx.x;
    const int by = blockIdx.y;

    const int ar = tid >> 2;            // 0..63
    const int ac = (tid & 3) << 2;      // 0,4,8,12
    const int br = tid >> 5;            // 0..7
    const int bc = (tid & 31) << 2;     // 0..124
    const int ty = tid >> 4;            // 0..15
    const int tx = tid & 15;            // 0..15

    const float* Ab = A + (size_t)(by * 128) * K;
    const float* Bb = B + bx * 128;

    ull accp[8][4];
#pragma unroll
    for (int i = 0; i < 8; i++)
#pragma unroll
        for (int j = 0; j < 4; j++) accp[i][j] = 0ull;

    for (int k0 = 0; k0 < K; k0 += 16) {
        float4 a0 = *(const float4*)(Ab + (size_t)ar * K + k0 + ac);
        float4 a1 = *(const float4*)(Ab + (size_t)(ar + 64) * K + k0 + ac);
        As[ac + 0][ar] = a0.x; As[ac + 1][ar] = a0.y;
        As[ac + 2][ar] = a0.z; As[ac + 3][ar] = a0.w;
        As[ac + 0][ar + 64] = a1.x; As[ac + 1][ar + 64] = a1.y;
        As[ac + 2][ar + 64] = a1.z; As[ac + 3][ar + 64] = a1.w;
        float4 b0 = *(const float4*)(Bb + (size_t)(k0 + br) * N + bc);
        float4 b1 = *(const float4*)(Bb + (size_t)(k0 + br + 8) * N + bc);
        *(float4*)&Bs[br][bc]     = b0;
        *(float4*)&Bs[br + 8][bc] = b1;
        __syncthreads();

#pragma unroll
        for (int kk = 0; kk < 16; kk++) {
            float a[8];
            *(float4*)(a)     = *(const float4*)&As[kk][ty * 8];
            *(float4*)(a + 4) = *(const float4*)&As[kk][ty * 8 + 4];
            // B pairs loaded directly as packed 64-bit lanes (no packing needed)
            ulonglong2 bq0 = *(const ulonglong2*)&Bs[kk][tx * 8];
            ulonglong2 bq1 = *(const ulonglong2*)&Bs[kk][tx * 8 + 4];
            ull bp0 = bq0.x, bp1 = bq0.y, bp2 = bq1.x, bp3 = bq1.y;
#pragma unroll
            for (int i = 0; i < 8; i++) {
                ull ad; PK2(ad, a[i], a[i]);
                FMA2(accp[i][0], ad, bp0, accp[i][0]);
                FMA2(accp[i][1], ad, bp1, accp[i][1]);
                FMA2(accp[i][2], ad, bp2, accp[i][2]);
                FMA2(accp[i][3], ad, bp3, accp[i][3]);
            }
        }
        __syncthreads();
    }

    float* Cb = C + (size_t)(by * 128 + ty * 8) * N + bx * 128 + tx * 8;
#pragma unroll
    for (int i = 0; i < 8; i++) {
        ulonglong2 o0, o1;
        o0.x = accp[i][0]; o0.y = accp[i][1];
        o1.x = accp[i][2]; o1.y = accp[i][3];
        *(ulonglong2*)(Cb + (size_t)i * N)     = o0;
        *(ulonglong2*)(Cb + (size_t)i * N + 4) = o1;
    }
}

// ---------------- RMSNorm for q1/q2: QQ(B,T,2048) -> g_q1/g_q2 (B,H,T,64) --
__global__ void rms_q(const float* __restrict__ qn1, const float* __restrict__ qn2)
{
    int item = blockIdx.x * 8 + (threadIdx.x >> 5);
    int lane = threadIdx.x & 31;
    int half = item & 1;
    int h = (item >> 1) & (HH - 1);
    int t = (item >> 5) & (TT - 1);
    int b = item >> 15;
    const float* src = g_QQ + (size_t)(b * TT + t) * 2048 + half * 1024 + h * 64;
    float v0 = src[lane], v1 = src[lane + 32];
    float ss = v0 * v0 + v1 * v1;
    ss += __shfl_xor_sync(0xffffffffu, ss, 16);
    ss += __shfl_xor_sync(0xffffffffu, ss, 8);
    ss += __shfl_xor_sync(0xffffffffu, ss, 4);
    ss += __shfl_xor_sync(0xffffffffu, ss, 2);
    ss += __shfl_xor_sync(0xffffffffu, ss, 1);
    float inv = rsqrtf(ss * (1.0f / 64.0f) + 1e-5f);
    const float* w = half ? qn2 : qn1;
    float* dst = (half ? g_q2 : g_q1) + (size_t)((b * HH + h) * TT + t) * 64;
    dst[lane]      = v0 * inv * w[lane];
    dst[lane + 32] = v1 * inv * w[lane + 32];
}

// ------- RMSNorm for k1/k2 + copy v: KV(B,T,3072) -> g_k1/g_k2/g_v --------
__global__ void rms_kv(const float* __restrict__ kn1, const float* __restrict__ kn2)
{
    int item = blockIdx.x * 8 + (threadIdx.x >> 5);
    int lane = threadIdx.x & 31;
    int part = item % 3;
    int rest = item / 3;
    int h = rest & (HH - 1);
    int t = (rest >> 4) & (TT - 1);
    int b = rest >> 14;
    const float* src = g_KV + (size_t)(b * TT + t) * 3072 + part * 1024 + h * 64;
    float v0 = src[lane], v1 = src[lane + 32];
    size_t doff = (size_t)((b * HH + h) * TT + t) * 64;
    if (part == 2) {
        g_v[doff + lane] = v0;
        g_v[doff + lane + 32] = v1;
        return;
    }
    float ss = v0 * v0 + v1 * v1;
    ss += __shfl_xor_sync(0xffffffffu, ss, 16);
    ss += __shfl_xor_sync(0xffffffffu, ss, 8);
    ss += __shfl_xor_sync(0xffffffffu, ss, 4);
    ss += __shfl_xor_sync(0xffffffffu, ss, 2);
    ss += __shfl_xor_sync(0xffffffffu, ss, 1);
    float inv = rsqrtf(ss * (1.0f / 64.0f) + 1e-5f);
    const float* w = part ? kn2 : kn1;
    float* dst = (part ? g_k2 : g_k1) + doff;
    dst[lane]      = v0 * inv * w[lane];
    dst[lane + 32] = v1 * inv * w[lane + 32];
}

// ---------------- flash attention, 4x4 register tiling + FFMA2 -------------
// Smem: Qt/Kt transposed [d][row] stride PS; V row-major [c][d]; P row-major.
#define PS 68
#define ATTN_SMEM (6 * 64 * PS * 4)     // 104448 bytes

__device__ __forceinline__ void attn_branch(
    const float* __restrict__ Qt, const float* __restrict__ Kt,
    const float* __restrict__ Vs, float* __restrict__ Ps,
    int ty, int tx, float* m, float* l, ull (*accp)[2])
{
    // ---- S = Q K^T : 4 rows (ty*4+i) x 4 cols (tx*4+j) per thread ----
    ull sp[4][2];
#pragma unroll
    for (int i = 0; i < 4; i++) { sp[i][0] = 0ull; sp[i][1] = 0ull; }
    const float* qp = Qt + ty * 4;
    const float* kp = Kt + tx * 4;
#pragma unroll 8
    for (int d = 0; d < 64; d++) {
        float4 qv = *(const float4*)(qp + d * PS);
        ulonglong2 kq = *(const ulonglong2*)(kp + d * PS);
        ull ka = kq.x, kb = kq.y;
        ull q0, q1, q2, q3;
        PK2(q0, qv.x, qv.x); PK2(q1, qv.y, qv.y);
        PK2(q2, qv.z, qv.z); PK2(q3, qv.w, qv.w);
        FMA2(sp[0][0], q0, ka, sp[0][0]); FMA2(sp[0][1], q0, kb, sp[0][1]);
        FMA2(sp[1][0], q1, ka, sp[1][0]); FMA2(sp[1][1], q1, kb, sp[1][1]);
        FMA2(sp[2][0], q2, ka, sp[2][0]); FMA2(sp[2][1], q2, kb, sp[2][1]);
        FMA2(sp[3][0], q3, ka, sp[3][0]); FMA2(sp[3][1], q3, kb, sp[3][1]);
    }
    float s[4][4];
#pragma unroll
    for (int i = 0; i < 4; i++) {
        UPK2(s[i][0], s[i][1], sp[i][0]);
        UPK2(s[i][2], s[i][3], sp[i][1]);
    }
    // ---- online softmax (rows live in 16-lane groups: lanes share ty) ----
    float mloc[4];
#pragma unroll
    for (int i = 0; i < 4; i++) {
#pragma unroll
        for (int j = 0; j < 4; j++) s[i][j] *= 0.125f;
        mloc[i] = fmaxf(fmaxf(s[i][0], s[i][1]), fmaxf(s[i][2], s[i][3]));
    }
#pragma unroll
    for (int off = 1; off <= 8; off <<= 1)
#pragma unroll
        for (int i = 0; i < 4; i++)
            mloc[i] = fmaxf(mloc[i], __shfl_xor_sync(0xffffffffu, mloc[i], off));
    float al[4], ls[4];
#pragma unroll
    for (int i = 0; i < 4; i++) {
        float mn = fmaxf(m[i], mloc[i]);
        al[i] = __expf(m[i] - mn);
        m[i] = mn;
#pragma unroll
        for (int j = 0; j < 4; j++) s[i][j] = __expf(s[i][j] - mn);
        ls[i] = (s[i][0] + s[i][1]) + (s[i][2] + s[i][3]);
    }
#pragma unroll
    for (int off = 1; off <= 8; off <<= 1)
#pragma unroll
        for (int i = 0; i < 4; i++)
            ls[i] += __shfl_xor_sync(0xffffffffu, ls[i], off);
#pragma unroll
    for (int i = 0; i < 4; i++) l[i] = l[i] * al[i] + ls[i];
    // ---- stage P (row-major) ----
#pragma unroll
    for (int i = 0; i < 4; i++)
        *(float4*)(Ps + (ty * 4 + i) * PS + tx * 4) =
            make_float4(s[i][0], s[i][1], s[i][2], s[i][3]);
    __syncthreads();
    // ---- PV : acc[4 rows][4 dims], rescale then accumulate ----
#pragma unroll
    for (int i = 0; i < 4; i++) {
        ull ad; PK2(ad, al[i], al[i]);
        MUL2(accp[i][0], accp[i][0], ad);
        MUL2(accp[i][1], accp[i][1], ad);
    }
    const float* vp = Vs + tx * 4;
#pragma unroll 4
    for (int c0 = 0; c0 < 64; c0 += 4) {
        float4 p0 = *(const float4*)(Ps + (ty * 4 + 0) * PS + c0);
        float4 p1 = *(const float4*)(Ps + (ty * 4 + 1) * PS + c0);
        float4 p2 = *(const float4*)(Ps + (ty * 4 + 2) * PS + c0);
        float4 p3 = *(const float4*)(Ps + (ty * 4 + 3) * PS + c0);
#pragma unroll
        for (int k = 0; k < 4; k++) {
            ulonglong2 vq = *(const ulonglong2*)(vp + (c0 + k) * PS);
            ull va = vq.x, vb = vq.y;
            float pk0 = (k == 0) ? p0.x : (k == 1) ? p0.y : (k == 2) ? p0.z : p0.w;
            float pk1 = (k == 0) ? p1.x : (k == 1) ? p1.y : (k == 2) ? p1.z : p1.w;
            float pk2 = (k == 0) ? p2.x : (k == 1) ? p2.y : (k == 2) ? p2.z : p2.w;
            float pk3 = (k == 0) ? p3.x : (k == 1) ? p3.y : (k == 2) ? p3.z : p3.w;
            ull d0, d1, d2, d3;
            PK2(d0, pk0, pk0); PK2(d1, pk1, pk1);
            PK2(d2, pk2, pk2); PK2(d3, pk3, pk3);
            FMA2(accp[0][0], d0, va, accp[0][0]); FMA2(accp[0][1], d0, vb, accp[0][1]);
            FMA2(accp[1][0], d1, va, accp[1][0]); FMA2(accp[1][1], d1, vb, accp[1][1]);
            FMA2(accp[2][0], d2, va, accp[2][0]); FMA2(accp[2][1], d2, vb, accp[2][1]);
            FMA2(accp[3][0], d3, va, accp[3][0]); FMA2(accp[3][1], d3, vb, accp[3][1]);
        }
    }
    __syncthreads();   // protect Ps / tiles before reuse
}

__global__ __launch_bounds__(256, 2)
void attn_kernel(const float* __restrict__ lmb)
{
    extern __shared__ float sm[];
    float* Qt1 = sm;
    float* Qt2 = sm + 1 * 64 * PS;
    float* Kt1 = sm + 2 * 64 * PS;
    float* Kt2 = sm + 3 * 64 * PS;
    float* Vs  = sm + 4 * 64 * PS;
    float* Ps  = sm + 5 * 64 * PS;

    const int tid = threadIdx.x;
    const int ty = tid >> 4, tx = tid & 15;
    const int qt = blockIdx.x, h = blockIdx.y, b = blockIdx.z;
    const size_t bh = (size_t)(b * HH + h) * (TT * HD);

    {   // transpose-load Q tiles: row-fastest mapping => conflict-free STS
        size_t qbase = bh + (size_t)qt * 64 * 64;
        for (int idx = tid; idx < 1024; idx += 256) {
            int row = idx & 63, d4 = (idx >> 6) << 2;
            float4 v1 = *(const float4*)(g_q1 + qbase + row * 64 + d4);
            float4 v2 = *(const float4*)(g_q2 + qbase + row * 64 + d4);
            Qt1[(d4 + 0) * PS + row] = v1.x; Qt1[(d4 + 1) * PS + row] = v1.y;
            Qt1[(d4 + 2) * PS + row] = v1.z; Qt1[(d4 + 3) * PS + row] = v1.w;
            Qt2[(d4 + 0) * PS + row] = v2.x; Qt2[(d4 + 1) * PS + row] = v2.y;
            Qt2[(d4 + 2) * PS + row] = v2.z; Qt2[(d4 + 3) * PS + row] = v2.w;
        }
    }

    float m1[4], l1[4], m2[4], l2[4];
    ull accp1[4][2], accp2[4][2];
#pragma unroll
    for (int i = 0; i < 4; i++) {
        m1[i] = -1e30f; l1[i] = 0.f; m2[i] = -1e30f; l2[i] = 0.f;
        accp1[i][0] = accp1[i][1] = 0ull;
        accp2[i][0] = accp2[i][1] = 0ull;
    }

    for (int kt = 0; kt < 16; kt++) {
        __syncthreads();
        size_t kbase = bh + (size_t)kt * 64 * 64;
        for (int idx = tid; idx < 1024; idx += 256) {
            int row = idx & 63, d4 = (idx >> 6) << 2;
            float4 v1 = *(const float4*)(g_k1 + kbase + row * 64 + d4);
            float4 v2 = *(const float4*)(g_k2 + kbase + row * 64 + d4);
            Kt1[(d4 + 0) * PS + row] = v1.x; Kt1[(d4 + 1) * PS + row] = v1.y;
            Kt1[(d4 + 2) * PS + row] = v1.z; Kt1[(d4 + 3) * PS + row] = v1.w;
            Kt2[(d4 + 0) * PS + row] = v2.x; Kt2[(d4 + 1) * PS + row] = v2.y;
            Kt2[(d4 + 2) * PS + row] = v2.z; Kt2[(d4 + 3) * PS + row] = v2.w;
            int vr = idx >> 4, vc = (idx & 15) << 2;   // V row-major
            *(float4*)(Vs + vr * PS + vc) = *(const float4*)(g_v + kbase + vr * 64 + vc);
        }
        __syncthreads();
        attn_branch(Qt1, Kt1, Vs, Ps, ty, tx, m1, l1, accp1);
        attn_branch(Qt2, Kt2, Vs, Ps, ty, tx, m2, l2, accp2);
    }

    float cH = log1pf(__expf(lmb[h]));
#pragma unroll
    for (int i = 0; i < 4; i++) {
        float inv1 = 1.f / l1[i], inv2 = 1.f / l2[i];
        float a0, a1, a2, a3, b0, b1, b2, b3;
        UPK2(a0, a1, accp1[i][0]); UPK2(a2, a3, accp1[i][1]);
        UPK2(b0, b1, accp2[i][0]); UPK2(b2, b3, accp2[i][1]);
        float4 o;
        o.x = a0 * inv1 - cH * b0 * inv2;
        o.y = a1 * inv1 - cH * b1 * inv2;
        o.z = a2 * inv1 - cH * b2 * inv2;
        o.w = a3 * inv1 - cH * b3 * inv2;
        size_t obase = bh + (size_t)(qt * 64 + ty * 4 + i) * 64 + tx * 4;
        *(float4*)(g_y + obase) = o;
    }
}

// ---------------- GroupNorm per (b,h) over (T, HD), then relayout ----------
__global__ void groupnorm_kernel(const float* __restrict__ gn_w,
                                 const float* __restrict__ gn_b)
{
    __shared__ float rs[256], rq[256];
    const int bh = blockIdx.x;
    const float* src = g_y + (size_t)bh * TT * HD;
    const int tid = threadIdx.x;
    float s = 0.f, sq = 0.f;
    for (int i = tid; i < TT * HD; i += 256) {
        float v = src[i]; s += v; sq += v * v;
    }
    rs[tid] = s; rq[tid] = sq;
    __syncthreads();
    for (int off = 128; off > 0; off >>= 1) {
        if (tid < off) { rs[tid] += rs[tid + off]; rq[tid] += rq[tid + off]; }
        __syncthreads();
    }
    float mu  = rs[0] * (1.f / 65536.f);
    float var = rq[0] * (1.f / 65536.f) - mu * mu;
    float inv = rsqrtf(var + 1e-5f);
    int b = bh >> 4, h = bh & 15;
    for (int i = tid; i < TT * HD; i += 256) {
        int t = i >> 6, d = i & 63;
        float v = (src[i] - mu) * inv;
        g_yt[(size_t)(b * TT + t) * DD + h * 64 + d] =
            v * gn_w[h * 64 + d] + gn_b[h * 64 + d];
    }
}

// ---------------------------------------------------------------------------
extern "C" void kernel_launch(void* const* d_in, const int* in_sizes, int n_in,
                              void* d_out, int out_size)
{
    const float* x_q  = (const float*)d_in[0];
    const float* x_kv = (const float*)d_in[1];
    const float* Wq   = (const float*)d_in[2];
    const float* Wkv  = (const float*)d_in[3];
    const float* Wc   = (const float*)d_in[4];
    const float* qn1  = (const float*)d_in[5];
    const float* kn1  = (const float*)d_in[6];
    const float* qn2  = (const float*)d_in[7];
    const float* kn2  = (const float*)d_in[8];
    const float* gn_w = (const float*)d_in[9];
    const float* gn_b = (const float*)d_in[10];
    const float* lmb  = (const float*)d_in[11];
    float* out = (float*)d_out;
    (void)in_sizes; (void)n_in; (void)out_size;

    float *QQ, *KV, *YT;
    cudaGetSymbolAddress((void**)&QQ, g_QQ);
    cudaGetSymbolAddress((void**)&KV, g_KV);
    cudaGetSymbolAddress((void**)&YT, g_yt);

    cudaFuncSetAttribute(attn_kernel,
        cudaFuncAttributeMaxDynamicSharedMemorySize, ATTN_SMEM);

    sgemm<<<dim3(2048 / 128, 4096 / 128), 256>>>(x_q,  Wq,  QQ, 4096, 2048, 1024);
    sgemm<<<dim3(3072 / 128, 4096 / 128), 256>>>(x_kv, Wkv, KV, 4096, 3072, 1024);
    rms_q <<<16384, 256>>>(qn1, qn2);
    rms_kv<<<24576, 256>>>(kn1, kn2);
    attn_kernel<<<dim3(16, 16, 4), 256, ATTN_SMEM>>>(lmb);
    groupnorm_kernel<<<64, 256>>>(gn_w, gn_b);
    sgemm<<<dim3(1024 / 128, 4096 / 128), 256>>>(YT, Wc, out, 4096, 1024, 1024);
}

// round 5
// speedup vs baseline: 4.6599x; 1.5531x over previous
#include <cuda_runtime.h>
#include <cuda_bf16.h>
#include <math.h>
#include <stdint.h>

#define BB 4
#define TT 1024
#define DD 1024
#define HH 16
#define HD 64

typedef unsigned long long ull;

// ---- packed f32x2 helpers (SASS FFMA2 path) ----
#define FMA2(d,a,b,c) asm("fma.rn.f32x2 %0, %1, %2, %3;" : "=l"(d) : "l"(a), "l"(b), "l"(c))
#define MUL2(d,a,b)   asm("mul.rn.f32x2 %0, %1, %2;"     : "=l"(d) : "l"(a), "l"(b))
#define PK2(d,lo,hi)  asm("mov.b64 %0, {%1, %2};" : "=l"(d) : "f"(lo), "f"(hi))
#define UPK2(lo,hi,s) asm("mov.b64 {%0, %1}, %2;" : "=f"(lo), "=f"(hi) : "l"(s))

// ---------------- scratch (device globals; no allocation allowed) ----------
__device__ float g_QQ[BB*TT*2*DD];     // x_q @ Wq   (B,T,2048)
__device__ float g_KV[BB*TT*3*DD];     // x_kv @ Wkv (B,T,3072)
__device__ float g_q1[BB*HH*TT*HD];
__device__ float g_q2[BB*HH*TT*HD];
__device__ float g_k1[BB*HH*TT*HD];
__device__ float g_k2[BB*HH*TT*HD];
__device__ float g_v [BB*HH*TT*HD];
__device__ float g_y [BB*HH*TT*HD];
__device__ float g_yt[BB*TT*DD];
// bf16 split operands (reused serially across the three GEMMs)
__device__ __nv_bfloat16 g_AH[4096*1024];
__device__ __nv_bfloat16 g_AL[4096*1024];
__device__ __nv_bfloat16 g_BH[3072*1024];   // stored transposed: [N,K]
__device__ __nv_bfloat16 g_BL[3072*1024];

// =================== small asm helpers =====================================
__device__ __forceinline__ uint32_t s2u(const void* p) {
    uint32_t a;
    asm("{ .reg .u64 t; cvta.to.shared.u64 t, %1; cvt.u32.u64 %0, t; }" : "=r"(a) : "l"(p));
    return a;
}
__device__ __forceinline__ void cpa16(uint32_t d, const void* s) {
    asm volatile("cp.async.cg.shared.global [%0], [%1], 16;" :: "r"(d), "l"(s));
}
__device__ __forceinline__ void ldsm4(uint32_t* r, uint32_t a) {
    asm volatile("ldmatrix.sync.aligned.m8n8.x4.shared.b16 {%0,%1,%2,%3}, [%4];"
                 : "=r"(r[0]), "=r"(r[1]), "=r"(r[2]), "=r"(r[3]) : "r"(a));
}
#define MMA_BF16(d, a, b)                                                     \
    asm volatile("mma.sync.aligned.m16n8k16.row.col.f32.bf16.bf16.f32 "       \
        "{%0,%1,%2,%3}, {%4,%5,%6,%7}, {%8,%9}, {%0,%1,%2,%3};"               \
        : "+f"((d)[0]), "+f"((d)[1]), "+f"((d)[2]), "+f"((d)[3])              \
        : "r"((a)[0]), "r"((a)[1]), "r"((a)[2]), "r"((a)[3]),                 \
          "r"((b)[0]), "r"((b)[1]))

__device__ __forceinline__ uint32_t swz(uint32_t bo) {
    return bo ^ ((bo >> 3) & 0x70);
}

// =================== fp32 -> bf16 hi/lo split kernels ======================
__global__ void convA(const float* __restrict__ X, __nv_bfloat16* __restrict__ H,
                      __nv_bfloat16* __restrict__ L)
{
    int i = (blockIdx.x * 256 + threadIdx.x) * 4;
    float4 v = *(const float4*)(X + i);
    __nv_bfloat16 h0 = __float2bfloat16(v.x), h1 = __float2bfloat16(v.y);
    __nv_bfloat16 h2 = __float2bfloat16(v.z), h3 = __float2bfloat16(v.w);
    __nv_bfloat16 l0 = __float2bfloat16(v.x - __bfloat162float(h0));
    __nv_bfloat16 l1 = __float2bfloat16(v.y - __bfloat162float(h1));
    __nv_bfloat16 l2 = __float2bfloat16(v.z - __bfloat162float(h2));
    __nv_bfloat16 l3 = __float2bfloat16(v.w - __bfloat162float(h3));
    *(__nv_bfloat162*)(H + i)     = __nv_bfloat162(h0, h1);
    *(__nv_bfloat162*)(H + i + 2) = __nv_bfloat162(h2, h3);
    *(__nv_bfloat162*)(L + i)     = __nv_bfloat162(l0, l1);
    *(__nv_bfloat162*)(L + i + 2) = __nv_bfloat162(l2, l3);
}

// W [K,N] fp32 -> H/L [N,K] bf16 (transposed, for mma B operand)
__global__ void convBT(const float* __restrict__ W, __nv_bfloat16* __restrict__ H,
                       __nv_bfloat16* __restrict__ L, int K, int N)
{
    __shared__ float s[32][33];
    int nb = blockIdx.x * 32, kb = blockIdx.y * 32;
    int tx = threadIdx.x, ty = threadIdx.y;   // (32, 8)
#pragma unroll
    for (int i = 0; i < 4; i++)
        s[ty + i * 8][tx] = W[(size_t)(kb + ty + i * 8) * N + nb + tx];
    __syncthreads();
#pragma unroll
    for (int i = 0; i < 4; i++) {
        float v = s[tx][ty + i * 8];
        __nv_bfloat16 h = __float2bfloat16(v);
        __nv_bfloat16 l = __float2bfloat16(v - __bfloat162float(h));
        size_t o = (size_t)(nb + ty + i * 8) * K + kb + tx;
        H[o] = h; L[o] = l;
    }
}

// ============ bf16 split GEMM on mma.sync: C[M,N] = A[M,K] @ B^T[N,K] ======
// 128x128 CTA tile, BK=64, cp.async double buffer, 8 warps of 32x64.
// 3 products per chunk: AhBh + AhBl + AlBh  (ll term ~2^-18, dropped).
#define MG_STAGE 65536                  // 4 matrices x 16KB
#define MG_TOTAL (2 * MG_STAGE)         // 131072

__global__ __launch_bounds__(256, 1)
void mma_gemm(const __nv_bfloat16* __restrict__ Ah, const __nv_bfloat16* __restrict__ Al,
              const __nv_bfloat16* __restrict__ Bh, const __nv_bfloat16* __restrict__ Bl,
              float* __restrict__ C, int M, int N, int K)
{
    extern __shared__ char smem[];
    const uint32_t sb = s2u(smem);
    const int tid = threadIdx.x;
    const int wid = tid >> 5, lane = tid & 31;
    const int bx = blockIdx.x, by = blockIdx.y;
    const int wm = (wid & 3) * 32;      // warp M offset within tile
    const int wn = (wid >> 2) * 64;     // warp N offset

    const __nv_bfloat16* pAh = Ah + (size_t)(by * 128) * K;
    const __nv_bfloat16* pAl = Al + (size_t)(by * 128) * K;
    const __nv_bfloat16* pBh = Bh + (size_t)(bx * 128) * K;
    const __nv_bfloat16* pBl = Bl + (size_t)(bx * 128) * K;

    const int NC = K >> 6;

    // per-thread cp.async slots: idx -> (row, 16B-chunk)
    const int crow = (tid * 4) >> 3;            // reused pattern below instead

    float acc[2][8][4];
#pragma unroll
    for (int mf = 0; mf < 2; mf++)
#pragma unroll
        for (int nf = 0; nf < 8; nf++)
#pragma unroll
            for (int q = 0; q < 4; q++) acc[mf][nf][q] = 0.f;

    // ---- issue loads for one stage ----
    auto issue = [&](int ch, int st) {
        uint32_t stb = sb + st * MG_STAGE;
        int k0 = ch << 6;
#pragma unroll
        for (int it = 0; it < 4; it++) {
            int idx = tid + it * 256;
            int row = idx >> 3, c8 = idx & 7;
            uint32_t so = swz(row * 128 + c8 * 16);
            size_t go = (size_t)row * K + k0 + c8 * 8;
            cpa16(stb + 0 * 16384 + so, pAh + go);
            cpa16(stb + 1 * 16384 + so, pAl + go);
            cpa16(stb + 2 * 16384 + so, pBh + go);
            cpa16(stb + 3 * 16384 + so, pBl + go);
        }
        asm volatile("cp.async.commit_group;" ::: "memory");
    };
    (void)crow;

    issue(0, 0);

    // ldmatrix lane address components (constant across chunks)
    const int a_r  = lane & 15;                 // row within m16
    const int a_kb = (lane >> 4) * 16;          // k-half byte offset
    const int b_r  = (lane & 7) + ((lane >> 4) & 1) * 8;   // row within n16
    const int b_kb = ((lane >> 3) & 1) * 16;

    for (int ch = 0; ch < NC; ch++) {
        const int st = ch & 1;
        if (ch + 1 < NC) issue(ch + 1, st ^ 1);
        if (ch + 1 < NC)
            asm volatile("cp.async.wait_group 1;" ::: "memory");
        else
            asm volatile("cp.async.wait_group 0;" ::: "memory");
        __syncthreads();

        const uint32_t sAh = sb + st * MG_STAGE + 0 * 16384;
        const uint32_t sAl = sb + st * MG_STAGE + 1 * 16384;
        const uint32_t sBh = sb + st * MG_STAGE + 2 * 16384;
        const uint32_t sBl = sb + st * MG_STAGE + 3 * 16384;

#pragma unroll
        for (int ks = 0; ks < 4; ks++) {
            uint32_t aH[2][4], aL[2][4], bH[16], bL[16];
#pragma unroll
            for (int mf = 0; mf < 2; mf++) {
                uint32_t off = swz((wm + mf * 16 + a_r) * 128 + ks * 32 + a_kb);
                ldsm4(aH[mf], sAh + off);
                ldsm4(aL[mf], sAl + off);
            }
#pragma unroll
            for (int g = 0; g < 4; g++) {
                uint32_t off = swz((wn + g * 16 + b_r) * 128 + ks * 32 + b_kb);
                ldsm4(bH + g * 4, sBh + off);
                ldsm4(bL + g * 4, sBl + off);
            }
#pragma unroll
            for (int mf = 0; mf < 2; mf++)
#pragma unroll
                for (int nf = 0; nf < 8; nf++) {
                    MMA_BF16(acc[mf][nf], aH[mf], bH + nf * 2);
                    MMA_BF16(acc[mf][nf], aH[mf], bL + nf * 2);
                    MMA_BF16(acc[mf][nf], aL[mf], bH + nf * 2);
                }
        }
        __syncthreads();   // all warps done with stage st before it is refilled
    }

    // ---- epilogue: c(row = t/4 [+8], col = 2*(t%4)+{0,1}) ----
    const int er = lane >> 2, ec = (lane & 3) * 2;
#pragma unroll
    for (int mf = 0; mf < 2; mf++) {
#pragma unroll
        for (int nf = 0; nf < 8; nf++) {
            int row0 = by * 128 + wm + mf * 16 + er;
            int col  = bx * 128 + wn + nf * 8 + ec;
            float2 v0 = make_float2(acc[mf][nf][0], acc[mf][nf][1]);
            float2 v1 = make_float2(acc[mf][nf][2], acc[mf][nf][3]);
            *(float2*)(C + (size_t)row0 * N + col)       = v0;
            *(float2*)(C + (size_t)(row0 + 8) * N + col) = v1;
        }
    }
}

// ---------------- RMSNorm for q1/q2 ----------------------------------------
__global__ void rms_q(const float* __restrict__ qn1, const float* __restrict__ qn2)
{
    int item = blockIdx.x * 8 + (threadIdx.x >> 5);
    int lane = threadIdx.x & 31;
    int half = item & 1;
    int h = (item >> 1) & (HH - 1);
    int t = (item >> 5) & (TT - 1);
    int b = item >> 15;
    const float* src = g_QQ + (size_t)(b * TT + t) * 2048 + half * 1024 + h * 64;
    float v0 = src[lane], v1 = src[lane + 32];
    float ss = v0 * v0 + v1 * v1;
    ss += __shfl_xor_sync(0xffffffffu, ss, 16);
    ss += __shfl_xor_sync(0xffffffffu, ss, 8);
    ss += __shfl_xor_sync(0xffffffffu, ss, 4);
    ss += __shfl_xor_sync(0xffffffffu, ss, 2);
    ss += __shfl_xor_sync(0xffffffffu, ss, 1);
    float inv = rsqrtf(ss * (1.0f / 64.0f) + 1e-5f);
    const float* w = half ? qn2 : qn1;
    float* dst = (half ? g_q2 : g_q1) + (size_t)((b * HH + h) * TT + t) * 64;
    dst[lane]      = v0 * inv * w[lane];
    dst[lane + 32] = v1 * inv * w[lane + 32];
}

__global__ void rms_kv(const float* __restrict__ kn1, const float* __restrict__ kn2)
{
    int item = blockIdx.x * 8 + (threadIdx.x >> 5);
    int lane = threadIdx.x & 31;
    int part = item % 3;
    int rest = item / 3;
    int h = rest & (HH - 1);
    int t = (rest >> 4) & (TT - 1);
    int b = rest >> 14;
    const float* src = g_KV + (size_t)(b * TT + t) * 3072 + part * 1024 + h * 64;
    float v0 = src[lane], v1 = src[lane + 32];
    size_t doff = (size_t)((b * HH + h) * TT + t) * 64;
    if (part == 2) {
        g_v[doff + lane] = v0;
        g_v[doff + lane + 32] = v1;
        return;
    }
    float ss = v0 * v0 + v1 * v1;
    ss += __shfl_xor_sync(0xffffffffu, ss, 16);
    ss += __shfl_xor_sync(0xffffffffu, ss, 8);
    ss += __shfl_xor_sync(0xffffffffu, ss, 4);
    ss += __shfl_xor_sync(0xffffffffu, ss, 2);
    ss += __shfl_xor_sync(0xffffffffu, ss, 1);
    float inv = rsqrtf(ss * (1.0f / 64.0f) + 1e-5f);
    const float* w = part ? kn2 : kn1;
    float* dst = (part ? g_k2 : g_k1) + doff;
    dst[lane]      = v0 * inv * w[lane];
    dst[lane + 32] = v1 * inv * w[lane + 32];
}

// ---------------- flash attention, 4x4 register tiling + FFMA2 -------------
#define PS 68
#define ATTN_SMEM (6 * 64 * PS * 4)

__device__ __forceinline__ void attn_branch(
    const float* __restrict__ Qt, const float* __restrict__ Kt,
    const float* __restrict__ Vs, float* __restrict__ Ps,
    int ty, int tx, float* m, float* l, ull (*accp)[2])
{
    ull sp[4][2];
#pragma unroll
    for (int i = 0; i < 4; i++) { sp[i][0] = 0ull; sp[i][1] = 0ull; }
    const float* qp = Qt + ty * 4;
    const float* kp = Kt + tx * 4;
#pragma unroll 8
    for (int d = 0; d < 64; d++) {
        float4 qv = *(const float4*)(qp + d * PS);
        ulonglong2 kq = *(const ulonglong2*)(kp + d * PS);
        ull ka = kq.x, kb = kq.y;
        ull q0, q1, q2, q3;
        PK2(q0, qv.x, qv.x); PK2(q1, qv.y, qv.y);
        PK2(q2, qv.z, qv.z); PK2(q3, qv.w, qv.w);
        FMA2(sp[0][0], q0, ka, sp[0][0]); FMA2(sp[0][1], q0, kb, sp[0][1]);
        FMA2(sp[1][0], q1, ka, sp[1][0]); FMA2(sp[1][1], q1, kb, sp[1][1]);
        FMA2(sp[2][0], q2, ka, sp[2][0]); FMA2(sp[2][1], q2, kb, sp[2][1]);
        FMA2(sp[3][0], q3, ka, sp[3][0]); FMA2(sp[3][1], q3, kb, sp[3][1]);
    }
    float s[4][4];
#pragma unroll
    for (int i = 0; i < 4; i++) {
        UPK2(s[i][0], s[i][1], sp[i][0]);
        UPK2(s[i][2], s[i][3], sp[i][1]);
    }
    float mloc[4];
#pragma unroll
    for (int i = 0; i < 4; i++) {
#pragma unroll
        for (int j = 0; j < 4; j++) s[i][j] *= 0.125f;
        mloc[i] = fmaxf(fmaxf(s[i][0], s[i][1]), fmaxf(s[i][2], s[i][3]));
    }
#pragma unroll
    for (int off = 1; off <= 8; off <<= 1)
#pragma unroll
        for (int i = 0; i < 4; i++)
            mloc[i] = fmaxf(mloc[i], __shfl_xor_sync(0xffffffffu, mloc[i], off));
    float al[4], ls[4];
#pragma unroll
    for (int i = 0; i < 4; i++) {
        float mn = fmaxf(m[i], mloc[i]);
        al[i] = __expf(m[i] - mn);
        m[i] = mn;
#pragma unroll
        for (int j = 0; j < 4; j++) s[i][j] = __expf(s[i][j] - mn);
        ls[i] = (s[i][0] + s[i][1]) + (s[i][2] + s[i][3]);
    }
#pragma unroll
    for (int off = 1; off <= 8; off <<= 1)
#pragma unroll
        for (int i = 0; i < 4; i++)
            ls[i] += __shfl_xor_sync(0xffffffffu, ls[i], off);
#pragma unroll
    for (int i = 0; i < 4; i++) l[i] = l[i] * al[i] + ls[i];
#pragma unroll
    for (int i = 0; i < 4; i++)
        *(float4*)(Ps + (ty * 4 + i) * PS + tx * 4) =
            make_float4(s[i][0], s[i][1], s[i][2], s[i][3]);
    __syncthreads();
#pragma unroll
    for (int i = 0; i < 4; i++) {
        ull ad; PK2(ad, al[i], al[i]);
        MUL2(accp[i][0], accp[i][0], ad);
        MUL2(accp[i][1], accp[i][1], ad);
    }
    const float* vp = Vs + tx * 4;
#pragma unroll 4
    for (int c0 = 0; c0 < 64; c0 += 4) {
        float4 p0 = *(const float4*)(Ps + (ty * 4 + 0) * PS + c0);
        float4 p1 = *(const float4*)(Ps + (ty * 4 + 1) * PS + c0);
        float4 p2 = *(const float4*)(Ps + (ty * 4 + 2) * PS + c0);
        float4 p3 = *(const float4*)(Ps + (ty * 4 + 3) * PS + c0);
#pragma unroll
        for (int k = 0; k < 4; k++) {
            ulonglong2 vq = *(const ulonglong2*)(vp + (c0 + k) * PS);
            ull va = vq.x, vb = vq.y;
            float pk0 = (k == 0) ? p0.x : (k == 1) ? p0.y : (k == 2) ? p0.z : p0.w;
            float pk1 = (k == 0) ? p1.x : (k == 1) ? p1.y : (k == 2) ? p1.z : p1.w;
            float pk2 = (k == 0) ? p2.x : (k == 1) ? p2.y : (k == 2) ? p2.z : p2.w;
            float pk3 = (k == 0) ? p3.x : (k == 1) ? p3.y : (k == 2) ? p3.z : p3.w;
            ull d0, d1, d2, d3;
            PK2(d0, pk0, pk0); PK2(d1, pk1, pk1);
            PK2(d2, pk2, pk2); PK2(d3, pk3, pk3);
            FMA2(accp[0][0], d0, va, accp[0][0]); FMA2(accp[0][1], d0, vb, accp[0][1]);
            FMA2(accp[1][0], d1, va, accp[1][0]); FMA2(accp[1][1], d1, vb, accp[1][1]);
            FMA2(accp[2][0], d2, va, accp[2][0]); FMA2(accp[2][1], d2, vb, accp[2][1]);
            FMA2(accp[3][0], d3, va, accp[3][0]); FMA2(accp[3][1], d3, vb, accp[3][1]);
        }
    }
    __syncthreads();
}

__global__ __launch_bounds__(256, 2)
void attn_kernel(const float* __restrict__ lmb)
{
    extern __shared__ float sm[];
    float* Qt1 = sm;
    float* Qt2 = sm + 1 * 64 * PS;
    float* Kt1 = sm + 2 * 64 * PS;
    float* Kt2 = sm + 3 * 64 * PS;
    float* Vs  = sm + 4 * 64 * PS;
    float* Ps  = sm + 5 * 64 * PS;

    const int tid = threadIdx.x;
    const int ty = tid >> 4, tx = tid & 15;
    const int qt = blockIdx.x, h = blockIdx.y, b = blockIdx.z;
    const size_t bh = (size_t)(b * HH + h) * (TT * HD);

    {
        size_t qbase = bh + (size_t)qt * 64 * 64;
        for (int idx = tid; idx < 1024; idx += 256) {
            int row = idx & 63, d4 = (idx >> 6) << 2;
            float4 v1 = *(const float4*)(g_q1 + qbase + row * 64 + d4);
            float4 v2 = *(const float4*)(g_q2 + qbase + row * 64 + d4);
            Qt1[(d4 + 0) * PS + row] = v1.x; Qt1[(d4 + 1) * PS + row] = v1.y;
            Qt1[(d4 + 2) * PS + row] = v1.z; Qt1[(d4 + 3) * PS + row] = v1.w;
            Qt2[(d4 + 0) * PS + row] = v2.x; Qt2[(d4 + 1) * PS + row] = v2.y;
            Qt2[(d4 + 2) * PS + row] = v2.z; Qt2[(d4 + 3) * PS + row] = v2.w;
        }
    }

    float m1[4], l1[4], m2[4], l2[4];
    ull accp1[4][2], accp2[4][2];
#pragma unroll
    for (int i = 0; i < 4; i++) {
        m1[i] = -1e30f; l1[i] = 0.f; m2[i] = -1e30f; l2[i] = 0.f;
        accp1[i][0] = accp1[i][1] = 0ull;
        accp2[i][0] = accp2[i][1] = 0ull;
    }

    for (int kt = 0; kt < 16; kt++) {
        __syncthreads();
        size_t kbase = bh + (size_t)kt * 64 * 64;
        for (int idx = tid; idx < 1024; idx += 256) {
            int row = idx & 63, d4 = (idx >> 6) << 2;
            float4 v1 = *(const float4*)(g_k1 + kbase + row * 64 + d4);
            float4 v2 = *(const float4*)(g_k2 + kbase + row * 64 + d4);
            Kt1[(d4 + 0) * PS + row] = v1.x; Kt1[(d4 + 1) * PS + row] = v1.y;
            Kt1[(d4 + 2) * PS + row] = v1.z; Kt1[(d4 + 3) * PS + row] = v1.w;
            Kt2[(d4 + 0) * PS + row] = v2.x; Kt2[(d4 + 1) * PS + row] = v2.y;
            Kt2[(d4 + 2) * PS + row] = v2.z; Kt2[(d4 + 3) * PS + row] = v2.w;
            int vr = idx >> 4, vc = (idx & 15) << 2;
            *(float4*)(Vs + vr * PS + vc) = *(const float4*)(g_v + kbase + vr * 64 + vc);
        }
        __syncthreads();
        attn_branch(Qt1, Kt1, Vs, Ps, ty, tx, m1, l1, accp1);
        attn_branch(Qt2, Kt2, Vs, Ps, ty, tx, m2, l2, accp2);
    }

    float cH = log1pf(__expf(lmb[h]));
#pragma unroll
    for (int i = 0; i < 4; i++) {
        float inv1 = 1.f / l1[i], inv2 = 1.f / l2[i];
        float a0, a1, a2, a3, b0, b1, b2, b3;
        UPK2(a0, a1, accp1[i][0]); UPK2(a2, a3, accp1[i][1]);
        UPK2(b0, b1, accp2[i][0]); UPK2(b2, b3, accp2[i][1]);
        float4 o;
        o.x = a0 * inv1 - cH * b0 * inv2;
        o.y = a1 * inv1 - cH * b1 * inv2;
        o.z = a2 * inv1 - cH * b2 * inv2;
        o.w = a3 * inv1 - cH * b3 * inv2;
        size_t obase = bh + (size_t)(qt * 64 + ty * 4 + i) * 64 + tx * 4;
        *(float4*)(g_y + obase) = o;
    }
}

// ---------------- GroupNorm per (b,h) over (T, HD), then relayout ----------
__global__ void groupnorm_kernel(const float* __restrict__ gn_w,
                                 const float* __restrict__ gn_b)
{
    __shared__ float rs[256], rq[256];
    const int bh = blockIdx.x;
    const float* src = g_y + (size_t)bh * TT * HD;
    const int tid = threadIdx.x;
    float s = 0.f, sq = 0.f;
    for (int i = tid; i < TT * HD; i += 256) {
        float v = src[i]; s += v; sq += v * v;
    }
    rs[tid] = s; rq[tid] = sq;
    __syncthreads();
    for (int off = 128; off > 0; off >>= 1) {
        if (tid < off) { rs[tid] += rs[tid + off]; rq[tid] += rq[tid + off]; }
        __syncthreads();
    }
    float mu  = rs[0] * (1.f / 65536.f);
    float var = rq[0] * (1.f / 65536.f) - mu * mu;
    float inv = rsqrtf(var + 1e-5f);
    int b = bh >> 4, h = bh & 15;
    for (int i = tid; i < TT * HD; i += 256) {
        int t = i >> 6, d = i & 63;
        float v = (src[i] - mu) * inv;
        g_yt[(size_t)(b * TT + t) * DD + h * 64 + d] =
            v * gn_w[h * 64 + d] + gn_b[h * 64 + d];
    }
}

// ---------------------------------------------------------------------------
extern "C" void kernel_launch(void* const* d_in, const int* in_sizes, int n_in,
                              void* d_out, int out_size)
{
    const float* x_q  = (const float*)d_in[0];
    const float* x_kv = (const float*)d_in[1];
    const float* Wq   = (const float*)d_in[2];
    const float* Wkv  = (const float*)d_in[3];
    const float* Wc   = (const float*)d_in[4];
    const float* qn1  = (const float*)d_in[5];
    const float* kn1  = (const float*)d_in[6];
    const float* qn2  = (const float*)d_in[7];
    const float* kn2  = (const float*)d_in[8];
    const float* gn_w = (const float*)d_in[9];
    const float* gn_b = (const float*)d_in[10];
    const float* lmb  = (const float*)d_in[11];
    float* out = (float*)d_out;
    (void)in_sizes; (void)n_in; (void)out_size;

    float *QQ, *KV, *YT;
    __nv_bfloat16 *AH, *AL, *BH, *BL;
    cudaGetSymbolAddress((void**)&QQ, g_QQ);
    cudaGetSymbolAddress((void**)&KV, g_KV);
    cudaGetSymbolAddress((void**)&YT, g_yt);
    cudaGetSymbolAddress((void**)&AH, g_AH);
    cudaGetSymbolAddress((void**)&AL, g_AL);
    cudaGetSymbolAddress((void**)&BH, g_BH);
    cudaGetSymbolAddress((void**)&BL, g_BL);

    cudaFuncSetAttribute(attn_kernel,
        cudaFuncAttributeMaxDynamicSharedMemorySize, ATTN_SMEM);
    cudaFuncSetAttribute(mma_gemm,
        cudaFuncAttributeMaxDynamicSharedMemorySize, MG_TOTAL);

    // 1) QQ = x_q @ Wq  (bf16x3 split tensor-core GEMM)
    convA<<<4096, 256>>>(x_q, AH, AL);
    convBT<<<dim3(64, 32), dim3(32, 8)>>>(Wq, BH, BL, 1024, 2048);
    mma_gemm<<<dim3(16, 32), 256, MG_TOTAL>>>(AH, AL, BH, BL, QQ, 4096, 2048, 1024);
    // 2) KV = x_kv @ Wkv
    convA<<<4096, 256>>>(x_kv, AH, AL);
    convBT<<<dim3(96, 32), dim3(32, 8)>>>(Wkv, BH, BL, 1024, 3072);
    mma_gemm<<<dim3(24, 32), 256, MG_TOTAL>>>(AH, AL, BH, BL, KV, 4096, 3072, 1024);
    // 3) per-head RMSNorm + head-major relayout
    rms_q <<<16384, 256>>>(qn1, qn2);
    rms_kv<<<24576, 256>>>(kn1, kn2);
    // 4) differential flash attention
    attn_kernel<<<dim3(16, 16, 4), 256, ATTN_SMEM>>>(lmb);
    // 5) GroupNorm + relayout
    groupnorm_kernel<<<64, 256>>>(gn_w, gn_b);
    // 6) out = yt @ Wc
    convA<<<4096, 256>>>(YT, AH, AL);
    convBT<<<dim3(32, 32), dim3(32, 8)>>>(Wc, BH, BL, 1024, 1024);
    mma_gemm<<<dim3(8, 32), 256, MG_TOTAL>>>(AH, AL, BH, BL, out, 4096, 1024, 1024);
}

// round 8
// speedup vs baseline: 4.9848x; 1.0697x over previous
#include <cuda_runtime.h>
#include <cuda_bf16.h>
#include <math.h>
#include <stdint.h>

#define BB 4
#define TT 1024
#define DD 1024
#define HH 16
#define HD 64

typedef unsigned long long ull;

// ---------------- scratch (device globals; no allocation allowed) ----------
__device__ float g_QQ[BB*TT*2*DD];     // x_q @ Wq   (B,T,2048)
__device__ float g_KV[BB*TT*3*DD];     // x_kv @ Wkv (B,T,3072)
__device__ float g_y [BB*HH*TT*HD];    // attention out (B,H,T,64) fp32
__device__ float g_yt[BB*TT*DD];
// bf16 split operands for the projection GEMMs
__device__ __nv_bfloat16 g_AH[4096*1024];
__device__ __nv_bfloat16 g_AL[4096*1024];
__device__ __nv_bfloat16 g_BH[3072*1024];   // transposed: [N,K]
__device__ __nv_bfloat16 g_BL[3072*1024];
// bf16 hi/lo attention operands, (B,H,T,64)
#define AELE (BB*HH*TT*HD)
__device__ __nv_bfloat16 g_q1h[AELE], g_q1l[AELE], g_q2h[AELE], g_q2l[AELE];
__device__ __nv_bfloat16 g_k1h[AELE], g_k1l[AELE], g_k2h[AELE], g_k2l[AELE];
__device__ __nv_bfloat16 g_vh [AELE], g_vl [AELE];

// =================== small asm helpers =====================================
__device__ __forceinline__ uint32_t s2u(const void* p) {
    uint32_t a;
    asm("{ .reg .u64 t; cvta.to.shared.u64 t, %1; cvt.u32.u64 %0, t; }" : "=r"(a) : "l"(p));
    return a;
}
__device__ __forceinline__ void cpa16(uint32_t d, const void* s) {
    asm volatile("cp.async.cg.shared.global [%0], [%1], 16;" :: "r"(d), "l"(s));
}
__device__ __forceinline__ void ldsm4(uint32_t* r, uint32_t a) {
    asm volatile("ldmatrix.sync.aligned.m8n8.x4.shared.b16 {%0,%1,%2,%3}, [%4];"
                 : "=r"(r[0]), "=r"(r[1]), "=r"(r[2]), "=r"(r[3]) : "r"(a));
}
__device__ __forceinline__ void ldsm4t(uint32_t* r, uint32_t a) {
    asm volatile("ldmatrix.sync.aligned.m8n8.x4.trans.shared.b16 {%0,%1,%2,%3}, [%4];"
                 : "=r"(r[0]), "=r"(r[1]), "=r"(r[2]), "=r"(r[3]) : "r"(a));
}
#define MMA_BF16(d, a, b)                                                     \
    asm volatile("mma.sync.aligned.m16n8k16.row.col.f32.bf16.bf16.f32 "       \
        "{%0,%1,%2,%3}, {%4,%5,%6,%7}, {%8,%9}, {%0,%1,%2,%3};"               \
        : "+f"((d)[0]), "+f"((d)[1]), "+f"((d)[2]), "+f"((d)[3])              \
        : "r"((a)[0]), "r"((a)[1]), "r"((a)[2]), "r"((a)[3]),                 \
          "r"((b)[0]), "r"((b)[1]))
__device__ __forceinline__ uint32_t swz(uint32_t bo) {
    return bo ^ ((bo >> 3) & 0x70);
}
// pack hi-bf16 (truncation) of two fp32: low half = first elem
__device__ __forceinline__ uint32_t pkhi(float a, float b) {
    uint32_t d;
    asm("prmt.b32 %0, %1, %2, 0x7632;" : "=r"(d)
        : "r"(__float_as_uint(a)), "r"(__float_as_uint(b)));
    return d;
}
__device__ __forceinline__ uint32_t pkbf2(float lo, float hi) {
    uint32_t d;
    asm("cvt.rn.bf16x2.f32 %0, %1, %2;" : "=r"(d) : "f"(hi), "f"(lo));
    return d;
}
__device__ __forceinline__ float trunclo(float f) {
    return f - __uint_as_float(__float_as_uint(f) & 0xFFFF0000u);
}

// =================== fp32 -> bf16 hi/lo split kernels ======================
__global__ void convA(const float* __restrict__ X, __nv_bfloat16* __restrict__ H,
                      __nv_bfloat16* __restrict__ L)
{
    int i = (blockIdx.x * 256 + threadIdx.x) * 4;
    float4 v = *(const float4*)(X + i);
    __nv_bfloat16 h0 = __float2bfloat16(v.x), h1 = __float2bfloat16(v.y);
    __nv_bfloat16 h2 = __float2bfloat16(v.z), h3 = __float2bfloat16(v.w);
    __nv_bfloat16 l0 = __float2bfloat16(v.x - __bfloat162float(h0));
    __nv_bfloat16 l1 = __float2bfloat16(v.y - __bfloat162float(h1));
    __nv_bfloat16 l2 = __float2bfloat16(v.z - __bfloat162float(h2));
    __nv_bfloat16 l3 = __float2bfloat16(v.w - __bfloat162float(h3));
    *(__nv_bfloat162*)(H + i)     = __nv_bfloat162(h0, h1);
    *(__nv_bfloat162*)(H + i + 2) = __nv_bfloat162(h2, h3);
    *(__nv_bfloat162*)(L + i)     = __nv_bfloat162(l0, l1);
    *(__nv_bfloat162*)(L + i + 2) = __nv_bfloat162(l2, l3);
}

__global__ void convBT(const float* __restrict__ W, __nv_bfloat16* __restrict__ H,
                       __nv_bfloat16* __restrict__ L, int K, int N)
{
    __shared__ float s[32][33];
    int nb = blockIdx.x * 32, kb = blockIdx.y * 32;
    int tx = threadIdx.x, ty = threadIdx.y;
#pragma unroll
    for (int i = 0; i < 4; i++)
        s[ty + i * 8][tx] = W[(size_t)(kb + ty + i * 8) * N + nb + tx];
    __syncthreads();
#pragma unroll
    for (int i = 0; i < 4; i++) {
        float v = s[tx][ty + i * 8];
        __nv_bfloat16 h = __float2bfloat16(v);
        __nv_bfloat16 l = __float2bfloat16(v - __bfloat162float(h));
        size_t o = (size_t)(nb + ty + i * 8) * K + kb + tx;
        H[o] = h; L[o] = l;
    }
}

// ============ bf16 split GEMM on mma.sync (unchanged, validated) ===========
#define MG_STAGE 65536
#define MG_TOTAL (2 * MG_STAGE)

__global__ __launch_bounds__(256, 1)
void mma_gemm(const __nv_bfloat16* __restrict__ Ah, const __nv_bfloat16* __restrict__ Al,
              const __nv_bfloat16* __restrict__ Bh, const __nv_bfloat16* __restrict__ Bl,
              float* __restrict__ C, int M, int N, int K)
{
    extern __shared__ char smem[];
    const uint32_t sb = s2u(smem);
    const int tid = threadIdx.x;
    const int wid = tid >> 5, lane = tid & 31;
    const int bx = blockIdx.x, by = blockIdx.y;
    const int wm = (wid & 3) * 32;
    const int wn = (wid >> 2) * 64;

    const __nv_bfloat16* pAh = Ah + (size_t)(by * 128) * K;
    const __nv_bfloat16* pAl = Al + (size_t)(by * 128) * K;
    const __nv_bfloat16* pBh = Bh + (size_t)(bx * 128) * K;
    const __nv_bfloat16* pBl = Bl + (size_t)(bx * 128) * K;

    const int NC = K >> 6;

    float acc[2][8][4];
#pragma unroll
    for (int mf = 0; mf < 2; mf++)
#pragma unroll
        for (int nf = 0; nf < 8; nf++)
#pragma unroll
            for (int q = 0; q < 4; q++) acc[mf][nf][q] = 0.f;

    auto issue = [&](int ch, int st) {
        uint32_t stb = sb + st * MG_STAGE;
        int k0 = ch << 6;
#pragma unroll
        for (int it = 0; it < 4; it++) {
            int idx = tid + it * 256;
            int row = idx >> 3, c8 = idx & 7;
            uint32_t so = swz(row * 128 + c8 * 16);
            size_t go = (size_t)row * K + k0 + c8 * 8;
            cpa16(stb + 0 * 16384 + so, pAh + go);
            cpa16(stb + 1 * 16384 + so, pAl + go);
            cpa16(stb + 2 * 16384 + so, pBh + go);
            cpa16(stb + 3 * 16384 + so, pBl + go);
        }
        asm volatile("cp.async.commit_group;" ::: "memory");
    };

    issue(0, 0);

    const int a_r  = lane & 15;
    const int a_kb = (lane >> 4) * 16;
    const int b_r  = (lane & 7) + ((lane >> 4) & 1) * 8;
    const int b_kb = ((lane >> 3) & 1) * 16;

    for (int ch = 0; ch < NC; ch++) {
        const int st = ch & 1;
        if (ch + 1 < NC) issue(ch + 1, st ^ 1);
        if (ch + 1 < NC)
            asm volatile("cp.async.wait_group 1;" ::: "memory");
        else
            asm volatile("cp.async.wait_group 0;" ::: "memory");
        __syncthreads();

        const uint32_t sAh = sb + st * MG_STAGE + 0 * 16384;
        const uint32_t sAl = sb + st * MG_STAGE + 1 * 16384;
        const uint32_t sBh = sb + st * MG_STAGE + 2 * 16384;
        const uint32_t sBl = sb + st * MG_STAGE + 3 * 16384;

#pragma unroll
        for (int ks = 0; ks < 4; ks++) {
            uint32_t aH[2][4], aL[2][4], bH[16], bL[16];
#pragma unroll
            for (int mf = 0; mf < 2; mf++) {
                uint32_t off = swz((wm + mf * 16 + a_r) * 128 + ks * 32 + a_kb);
                ldsm4(aH[mf], sAh + off);
                ldsm4(aL[mf], sAl + off);
            }
#pragma unroll
            for (int g = 0; g < 4; g++) {
                uint32_t off = swz((wn + g * 16 + b_r) * 128 + ks * 32 + b_kb);
                ldsm4(bH + g * 4, sBh + off);
                ldsm4(bL + g * 4, sBl + off);
            }
#pragma unroll
            for (int mf = 0; mf < 2; mf++)
#pragma unroll
                for (int nf = 0; nf < 8; nf++) {
                    MMA_BF16(acc[mf][nf], aH[mf], bH + nf * 2);
                    MMA_BF16(acc[mf][nf], aH[mf], bL + nf * 2);
                    MMA_BF16(acc[mf][nf], aL[mf], bH + nf * 2);
                }
        }
        __syncthreads();
    }

    const int er = lane >> 2, ec = (lane & 3) * 2;
#pragma unroll
    for (int mf = 0; mf < 2; mf++) {
#pragma unroll
        for (int nf = 0; nf < 8; nf++) {
            int row0 = by * 128 + wm + mf * 16 + er;
            int col  = bx * 128 + wn + nf * 8 + ec;
            float2 v0 = make_float2(acc[mf][nf][0], acc[mf][nf][1]);
            float2 v1 = make_float2(acc[mf][nf][2], acc[mf][nf][3]);
            *(float2*)(C + (size_t)row0 * N + col)       = v0;
            *(float2*)(C + (size_t)(row0 + 8) * N + col) = v1;
        }
    }
}

// ---------------- RMSNorm -> bf16 hi/lo, head-major relayout ---------------
__global__ void rms_q(const float* __restrict__ qn1, const float* __restrict__ qn2)
{
    int item = blockIdx.x * 8 + (threadIdx.x >> 5);
    int lane = threadIdx.x & 31;
    int half = item & 1;
    int h = (item >> 1) & (HH - 1);
    int t = (item >> 5) & (TT - 1);
    int b = item >> 15;
    const float* src = g_QQ + (size_t)(b * TT + t) * 2048 + half * 1024 + h * 64;
    float v0 = src[lane], v1 = src[lane + 32];
    float ss = v0 * v0 + v1 * v1;
    ss += __shfl_xor_sync(0xffffffffu, ss, 16);
    ss += __shfl_xor_sync(0xffffffffu, ss, 8);
    ss += __shfl_xor_sync(0xffffffffu, ss, 4);
    ss += __shfl_xor_sync(0xffffffffu, ss, 2);
    ss += __shfl_xor_sync(0xffffffffu, ss, 1);
    float inv = rsqrtf(ss * (1.0f / 64.0f) + 1e-5f);
    const float* w = half ? qn2 : qn1;
    float r0 = v0 * inv * w[lane];
    float r1 = v1 * inv * w[lane + 32];
    size_t doff = (size_t)((b * HH + h) * TT + t) * 64;
    __nv_bfloat16* dh = (half ? g_q2h : g_q1h) + doff;
    __nv_bfloat16* dl = (half ? g_q2l : g_q1l) + doff;
    __nv_bfloat16 h0 = __float2bfloat16(r0), h1 = __float2bfloat16(r1);
    dh[lane]      = h0; dl[lane]      = __float2bfloat16(r0 - __bfloat162float(h0));
    dh[lane + 32] = h1; dl[lane + 32] = __float2bfloat16(r1 - __bfloat162float(h1));
}

__global__ void rms_kv(const float* __restrict__ kn1, const float* __restrict__ kn2)
{
    int item = blockIdx.x * 8 + (threadIdx.x >> 5);
    int lane = threadIdx.x & 31;
    int part = item % 3;
    int rest = item / 3;
    int h = rest & (HH - 1);
    int t = (rest >> 4) & (TT - 1);
    int b = rest >> 14;
    const float* src = g_KV + (size_t)(b * TT + t) * 3072 + part * 1024 + h * 64;
    float v0 = src[lane], v1 = src[lane + 32];
    size_t doff = (size_t)((b * HH + h) * TT + t) * 64;
    float r0, r1;
    __nv_bfloat16 *dh, *dl;
    if (part == 2) {
        r0 = v0; r1 = v1;
        dh = g_vh + doff; dl = g_vl + doff;
    } else {
        float ss = v0 * v0 + v1 * v1;
        ss += __shfl_xor_sync(0xffffffffu, ss, 16);
        ss += __shfl_xor_sync(0xffffffffu, ss, 8);
        ss += __shfl_xor_sync(0xffffffffu, ss, 4);
        ss += __shfl_xor_sync(0xffffffffu, ss, 2);
        ss += __shfl_xor_sync(0xffffffffu, ss, 1);
        float inv = rsqrtf(ss * (1.0f / 64.0f) + 1e-5f);
        const float* w = part ? kn2 : kn1;
        r0 = v0 * inv * w[lane];
        r1 = v1 * inv * w[lane + 32];
        dh = (part ? g_k2h : g_k1h) + doff;
        dl = (part ? g_k2l : g_k1l) + doff;
    }
    __nv_bfloat16 h0 = __float2bfloat16(r0), h1 = __float2bfloat16(r1);
    dh[lane]      = h0; dl[lane]      = __float2bfloat16(r0 - __bfloat162float(h0));
    dh[lane + 32] = h1; dl[lane + 32] = __float2bfloat16(r1 - __bfloat162float(h1));
}

// ================= tensor-core differential flash attention ================
// CTA: 128 q-rows x one (b,h). 8 warps x 16 rows. KV chunks of 128.
// Smem slots (16KB each): 0-3 Q1h,Q1l,Q2h,Q2l; 4-7 K1h,K1l,K2h,K2l; 8-9 Vh,Vl.
#define AT_SMEM (10 * 16384)

__global__ __launch_bounds__(256, 1)
void attn_mma(const float* __restrict__ lmb)
{
    extern __shared__ char smem[];
    const uint32_t sb = s2u(smem);
    const int tid = threadIdx.x;
    const int wid = tid >> 5, lane = tid & 31;
    const int qt = blockIdx.x, h = blockIdx.y, b = blockIdx.z;
    const size_t bh = (size_t)(b * HH + h) * (TT * HD);
    const int wm = wid * 16;

    // ---- Q tiles via cp.async ----
    {
        size_t qoff = bh + (size_t)qt * 128 * 64;
#pragma unroll
        for (int it = 0; it < 4; it++) {
            int idx = tid + it * 256;
            int row = idx >> 3, c8 = idx & 7;
            uint32_t so = swz(row * 128 + c8 * 16);
            size_t g = qoff + (size_t)row * 64 + c8 * 8;
            cpa16(sb + 0 * 16384 + so, g_q1h + g);
            cpa16(sb + 1 * 16384 + so, g_q1l + g);
            cpa16(sb + 2 * 16384 + so, g_q2h + g);
            cpa16(sb + 3 * 16384 + so, g_q2l + g);
        }
        asm volatile("cp.async.commit_group;" ::: "memory");
    }

    float o1[8][4], o2[8][4];
#pragma unroll
    for (int d = 0; d < 8; d++)
#pragma unroll
        for (int q = 0; q < 4; q++) { o1[d][q] = 0.f; o2[d][q] = 0.f; }
    float m1[2] = {-1e30f, -1e30f}, l1[2] = {0.f, 0.f};
    float m2[2] = {-1e30f, -1e30f}, l2[2] = {0.f, 0.f};

    const uint32_t a_off = (wm + (lane & 15)) * 128 + (lane >> 4) * 16;
    const uint32_t b_off = ((lane & 7) + ((lane >> 4) & 1) * 8) * 128
                         + ((lane >> 3) & 1) * 16;
    const uint32_t v_off = (lane & 15) * 128 + (lane >> 4) * 16;

    for (int kt = 0; kt < 8; kt++) {
        __syncthreads();   // previous chunk fully consumed
        {
            size_t kbase = bh + (size_t)kt * 128 * 64;
#pragma unroll
            for (int it = 0; it < 4; it++) {
                int idx = tid + it * 256;
                int row = idx >> 3, c8 = idx & 7;
                uint32_t so = swz(row * 128 + c8 * 16);
                size_t g = kbase + (size_t)row * 64 + c8 * 8;
                cpa16(sb + 4 * 16384 + so, g_k1h + g);
                cpa16(sb + 5 * 16384 + so, g_k1l + g);
                cpa16(sb + 6 * 16384 + so, g_k2h + g);
                cpa16(sb + 7 * 16384 + so, g_k2l + g);
                cpa16(sb + 8 * 16384 + so, g_vh + g);
                cpa16(sb + 9 * 16384 + so, g_vl + g);
            }
            asm volatile("cp.async.commit_group;" ::: "memory");
            asm volatile("cp.async.wait_group 0;" ::: "memory");
        }
        __syncthreads();

#pragma unroll
        for (int br = 0; br < 2; br++) {
            const uint32_t sAh = sb + (br ? 2 : 0) * 16384;
            const uint32_t sAl = sAh + 16384;
            const uint32_t sBh = sb + (br ? 6 : 4) * 16384;
            const uint32_t sBl = sBh + 16384;
            float* m = br ? m2 : m1;
            float* l = br ? l2 : l1;
            float (*o)[4] = br ? o2 : o1;

            // ---- S = Q K^T (3-product split) ----
            float sf[16][4];
#pragma unroll
            for (int nf = 0; nf < 16; nf++)
#pragma unroll
                for (int q = 0; q < 4; q++) sf[nf][q] = 0.f;
#pragma unroll
            for (int ks = 0; ks < 4; ks++) {
                uint32_t aH[4], aL[4];
                ldsm4(aH, sAh + swz(a_off + ks * 32));
                ldsm4(aL, sAl + swz(a_off + ks * 32));
#pragma unroll
                for (int g = 0; g < 8; g++) {
                    uint32_t bH[4], bL[4];
                    uint32_t off = swz(b_off + g * 2048 + ks * 32);
                    ldsm4(bH, sBh + off);
                    ldsm4(bL, sBl + off);
                    MMA_BF16(sf[2*g],   aH, bH);
                    MMA_BF16(sf[2*g],   aH, bL);
                    MMA_BF16(sf[2*g],   aL, bH);
                    MMA_BF16(sf[2*g+1], aH, bH + 2);
                    MMA_BF16(sf[2*g+1], aH, bL + 2);
                    MMA_BF16(sf[2*g+1], aL, bH + 2);
                }
            }

            // ---- online softmax (rows r0 = lane>>2, r1 = r0+8) ----
            float mx0 = -1e30f, mx1 = -1e30f;
#pragma unroll
            for (int nf = 0; nf < 16; nf++) {
                sf[nf][0] *= 0.125f; sf[nf][1] *= 0.125f;
                sf[nf][2] *= 0.125f; sf[nf][3] *= 0.125f;
                mx0 = fmaxf(mx0, fmaxf(sf[nf][0], sf[nf][1]));
                mx1 = fmaxf(mx1, fmaxf(sf[nf][2], sf[nf][3]));
            }
            mx0 = fmaxf(mx0, __shfl_xor_sync(0xffffffffu, mx0, 1));
            mx0 = fmaxf(mx0, __shfl_xor_sync(0xffffffffu, mx0, 2));
            mx1 = fmaxf(mx1, __shfl_xor_sync(0xffffffffu, mx1, 1));
            mx1 = fmaxf(mx1, __shfl_xor_sync(0xffffffffu, mx1, 2));
            float mn0 = fmaxf(m[0], mx0), mn1 = fmaxf(m[1], mx1);
            float al0 = __expf(m[0] - mn0), al1 = __expf(m[1] - mn1);
            float ls0 = 0.f, ls1 = 0.f;
#pragma unroll
            for (int nf = 0; nf < 16; nf++) {
                sf[nf][0] = __expf(sf[nf][0] - mn0); ls0 += sf[nf][0];
                sf[nf][1] = __expf(sf[nf][1] - mn0); ls0 += sf[nf][1];
                sf[nf][2] = __expf(sf[nf][2] - mn1); ls1 += sf[nf][2];
                sf[nf][3] = __expf(sf[nf][3] - mn1); ls1 += sf[nf][3];
            }
            ls0 += __shfl_xor_sync(0xffffffffu, ls0, 1);
            ls0 += __shfl_xor_sync(0xffffffffu, ls0, 2);
            ls1 += __shfl_xor_sync(0xffffffffu, ls1, 1);
            ls1 += __shfl_xor_sync(0xffffffffu, ls1, 2);
            l[0] = l[0] * al0 + ls0; m[0] = mn0;
            l[1] = l[1] * al1 + ls1; m[1] = mn1;
#pragma unroll
            for (int d = 0; d < 8; d++) {
                o[d][0] *= al0; o[d][1] *= al0;
                o[d][2] *= al1; o[d][3] *= al1;
            }

            // ---- O += P V (3-product split; P split in-register) ----
#pragma unroll
            for (int kf = 0; kf < 8; kf++) {
                float* f0 = sf[2*kf];
                float* f1 = sf[2*kf+1];
                uint32_t ph[4], pl[4];
                ph[0] = pkhi(f0[0], f0[1]);
                ph[1] = pkhi(f0[2], f0[3]);
                ph[2] = pkhi(f1[0], f1[1]);
                ph[3] = pkhi(f1[2], f1[3]);
                pl[0] = pkbf2(trunclo(f0[0]), trunclo(f0[1]));
                pl[1] = pkbf2(trunclo(f0[2]), trunclo(f0[3]));
                pl[2] = pkbf2(trunclo(f1[0]), trunclo(f1[1]));
                pl[3] = pkbf2(trunclo(f1[2]), trunclo(f1[3]));
#pragma unroll
                for (int d2 = 0; d2 < 4; d2++) {
                    uint32_t vH[4], vL[4];
                    uint32_t off = swz(v_off + kf * 2048 + d2 * 32);
                    ldsm4t(vH, sb + 8 * 16384 + off);
                    ldsm4t(vL, sb + 9 * 16384 + off);
                    MMA_BF16(o[d2*2],   ph, vH);
                    MMA_BF16(o[d2*2],   ph, vL);
                    MMA_BF16(o[d2*2],   pl, vH);
                    MMA_BF16(o[d2*2+1], ph, vH + 2);
                    MMA_BF16(o[d2*2+1], ph, vL + 2);
                    MMA_BF16(o[d2*2+1], pl, vH + 2);
                }
            }
        }
    }

    // ---- epilogue: y = O1/l1 - softplus(lmb)·O2/l2 ----
    float cH = log1pf(__expf(lmb[h]));
    float i10 = 1.f / l1[0], i11 = 1.f / l1[1];
    float i20 = 1.f / l2[0], i21 = 1.f / l2[1];
    const int er = lane >> 2, ec = (lane & 3) * 2;
#pragma unroll
    for (int d = 0; d < 8; d++) {
        size_t r0 = bh + (size_t)(qt * 128 + wm + er) * 64 + d * 8 + ec;
        size_t r1 = r0 + 8 * 64;
        float2 v0 = make_float2(o1[d][0] * i10 - cH * o2[d][0] * i20,
                                o1[d][1] * i10 - cH * o2[d][1] * i20);
        float2 v1 = make_float2(o1[d][2] * i11 - cH * o2[d][2] * i21,
                                o1[d][3] * i11 - cH * o2[d][3] * i21);
        *(float2*)(g_y + r0) = v0;
        *(float2*)(g_y + r1) = v1;
    }
}

// ---------------- GroupNorm per (b,h) over (T, HD), then relayout ----------
__global__ void groupnorm_kernel(const float* __restrict__ gn_w,
                                 const float* __restrict__ gn_b)
{
    __shared__ float rs[256], rq[256];
    const int bh = blockIdx.x;
    const float* src = g_y + (size_t)bh * TT * HD;
    const int tid = threadIdx.x;
    float s = 0.f, sq = 0.f;
    for (int i = tid; i < TT * HD; i += 256) {
        float v = src[i]; s += v; sq += v * v;
    }
    rs[tid] = s; rq[tid] = sq;
    __syncthreads();
    for (int off = 128; off > 0; off >>= 1) {
        if (tid < off) { rs[tid] += rs[tid + off]; rq[tid] += rq[tid + off]; }
        __syncthreads();
    }
    float mu  = rs[0] * (1.f / 65536.f);
    float var = rq[0] * (1.f / 65536.f) - mu * mu;
    float inv = rsqrtf(var + 1e-5f);
    int b = bh >> 4, h = bh & 15;
    for (int i = tid; i < TT * HD; i += 256) {
        int t = i >> 6, d = i & 63;
        float v = (src[i] - mu) * inv;
        g_yt[(size_t)(b * TT + t) * DD + h * 64 + d] =
            v * gn_w[h * 64 + d] + gn_b[h * 64 + d];
    }
}

// ---------------------------------------------------------------------------
extern "C" void kernel_launch(void* const* d_in, const int* in_sizes, int n_in,
                              void* d_out, int out_size)
{
    const float* x_q  = (const float*)d_in[0];
    const float* x_kv = (const float*)d_in[1];
    const float* Wq   = (const float*)d_in[2];
    const float* Wkv  = (const float*)d_in[3];
    const float* Wc   = (const float*)d_in[4];
    const float* qn1  = (const float*)d_in[5];
    const float* kn1  = (const float*)d_in[6];
    const float* qn2  = (const float*)d_in[7];
    const float* kn2  = (const float*)d_in[8];
    const float* gn_w = (const float*)d_in[9];
    const float* gn_b = (const float*)d_in[10];
    const float* lmb  = (const float*)d_in[11];
    float* out = (float*)d_out;
    (void)in_sizes; (void)n_in; (void)out_size;

    float *QQ, *KV, *YT;
    __nv_bfloat16 *AH, *AL, *BH, *BL;
    cudaGetSymbolAddress((void**)&QQ, g_QQ);
    cudaGetSymbolAddress((void**)&KV, g_KV);
    cudaGetSymbolAddress((void**)&YT, g_yt);
    cudaGetSymbolAddress((void**)&AH, g_AH);
    cudaGetSymbolAddress((void**)&AL, g_AL);
    cudaGetSymbolAddress((void**)&BH, g_BH);
    cudaGetSymbolAddress((void**)&BL, g_BL);

    cudaFuncSetAttribute(mma_gemm,
        cudaFuncAttributeMaxDynamicSharedMemorySize, MG_TOTAL);
    cudaFuncSetAttribute(attn_mma,
        cudaFuncAttributeMaxDynamicSharedMemorySize, AT_SMEM);

    // 1) QQ = x_q @ Wq
    convA<<<4096, 256>>>(x_q, AH, AL);
    convBT<<<dim3(64, 32), dim3(32, 8)>>>(Wq, BH, BL, 1024, 2048);
    mma_gemm<<<dim3(16, 32), 256, MG_TOTAL>>>(AH, AL, BH, BL, QQ, 4096, 2048, 1024);
    // 2) KV = x_kv @ Wkv
    convA<<<4096, 256>>>(x_kv, AH, AL);
    convBT<<<dim3(96, 32), dim3(32, 8)>>>(Wkv, BH, BL, 1024, 3072);
    mma_gemm<<<dim3(24, 32), 256, MG_TOTAL>>>(AH, AL, BH, BL, KV, 4096, 3072, 1024);
    // 3) per-head RMSNorm -> bf16 hi/lo, head-major
    rms_q <<<16384, 256>>>(qn1, qn2);
    rms_kv<<<24576, 256>>>(kn1, kn2);
    // 4) tensor-core differential flash attention
    attn_mma<<<dim3(8, 16, 4), 256, AT_SMEM>>>(lmb);
    // 5) GroupNorm + relayout
    groupnorm_kernel<<<64, 256>>>(gn_w, gn_b);
    // 6) out = yt @ Wc
    convA<<<4096, 256>>>(YT, AH, AL);
    convBT<<<dim3(32, 32), dim3(32, 8)>>>(Wc, BH, BL, 1024, 1024);
    mma_gemm<<<dim3(8, 32), 256, MG_TOTAL>>>(AH, AL, BH, BL, out, 4096, 1024, 1024);
}

// round 9
// speedup vs baseline: 7.9577x; 1.5964x over previous
#include <cuda_runtime.h>
#include <cuda_bf16.h>
#include <math.h>
#include <stdint.h>

#define BB 4
#define TT 1024
#define DD 1024
#define HH 16
#define HD 64

typedef unsigned long long ull;

// ---------------- scratch (device globals; no allocation allowed) ----------
__device__ float g_QQ[BB*TT*2*DD];     // x_q @ Wq   (B,T,2048)
__device__ float g_KV[BB*TT*3*DD];     // x_kv @ Wkv (B,T,3072)
__device__ float g_y [BB*HH*TT*HD];    // attention out (B,H,T,64) fp32
__device__ float g_yt[BB*TT*DD];
// bf16 split operands for the projection GEMMs
__device__ __nv_bfloat16 g_AH[4096*1024];
__device__ __nv_bfloat16 g_AL[4096*1024];
__device__ __nv_bfloat16 g_BH[3072*1024];   // transposed: [N,K]
__device__ __nv_bfloat16 g_BL[3072*1024];
// bf16 hi/lo attention operands, (B,H,T,64)
#define AELE (BB*HH*TT*HD)
__device__ __nv_bfloat16 g_q1h[AELE], g_q1l[AELE], g_q2h[AELE], g_q2l[AELE];
__device__ __nv_bfloat16 g_k1h[AELE], g_k1l[AELE], g_k2h[AELE], g_k2l[AELE];
__device__ __nv_bfloat16 g_vh [AELE], g_vl [AELE];

// =================== small asm helpers =====================================
__device__ __forceinline__ uint32_t s2u(const void* p) {
    uint32_t a;
    asm("{ .reg .u64 t; cvta.to.shared.u64 t, %1; cvt.u32.u64 %0, t; }" : "=r"(a) : "l"(p));
    return a;
}
__device__ __forceinline__ void cpa16(uint32_t d, const void* s) {
    asm volatile("cp.async.cg.shared.global [%0], [%1], 16;" :: "r"(d), "l"(s));
}
__device__ __forceinline__ void ldsm4(uint32_t* r, uint32_t a) {
    asm volatile("ldmatrix.sync.aligned.m8n8.x4.shared.b16 {%0,%1,%2,%3}, [%4];"
                 : "=r"(r[0]), "=r"(r[1]), "=r"(r[2]), "=r"(r[3]) : "r"(a));
}
__device__ __forceinline__ void ldsm4t(uint32_t* r, uint32_t a) {
    asm volatile("ldmatrix.sync.aligned.m8n8.x4.trans.shared.b16 {%0,%1,%2,%3}, [%4];"
                 : "=r"(r[0]), "=r"(r[1]), "=r"(r[2]), "=r"(r[3]) : "r"(a));
}
#define MMA_BF16(d, a, b)                                                     \
    asm volatile("mma.sync.aligned.m16n8k16.row.col.f32.bf16.bf16.f32 "       \
        "{%0,%1,%2,%3}, {%4,%5,%6,%7}, {%8,%9}, {%0,%1,%2,%3};"               \
        : "+f"((d)[0]), "+f"((d)[1]), "+f"((d)[2]), "+f"((d)[3])              \
        : "r"((a)[0]), "r"((a)[1]), "r"((a)[2]), "r"((a)[3]),                 \
          "r"((b)[0]), "r"((b)[1]))
__device__ __forceinline__ uint32_t swz(uint32_t bo) {
    return bo ^ ((bo >> 3) & 0x70);
}
__device__ __forceinline__ uint32_t pkhi(float a, float b) {
    uint32_t d;
    asm("prmt.b32 %0, %1, %2, 0x7632;" : "=r"(d)
        : "r"(__float_as_uint(a)), "r"(__float_as_uint(b)));
    return d;
}
__device__ __forceinline__ uint32_t pkbf2(float lo, float hi) {
    uint32_t d;
    asm("cvt.rn.bf16x2.f32 %0, %1, %2;" : "=r"(d) : "f"(hi), "f"(lo));
    return d;
}
__device__ __forceinline__ float trunclo(float f) {
    return f - __uint_as_float(__float_as_uint(f) & 0xFFFF0000u);
}

// =================== fp32 -> bf16 hi/lo split kernels ======================
__global__ void convA(const float* __restrict__ X, __nv_bfloat16* __restrict__ H,
                      __nv_bfloat16* __restrict__ L)
{
    int i = (blockIdx.x * 256 + threadIdx.x) * 4;
    float4 v = *(const float4*)(X + i);
    __nv_bfloat16 h0 = __float2bfloat16(v.x), h1 = __float2bfloat16(v.y);
    __nv_bfloat16 h2 = __float2bfloat16(v.z), h3 = __float2bfloat16(v.w);
    __nv_bfloat16 l0 = __float2bfloat16(v.x - __bfloat162float(h0));
    __nv_bfloat16 l1 = __float2bfloat16(v.y - __bfloat162float(h1));
    __nv_bfloat16 l2 = __float2bfloat16(v.z - __bfloat162float(h2));
    __nv_bfloat16 l3 = __float2bfloat16(v.w - __bfloat162float(h3));
    *(__nv_bfloat162*)(H + i)     = __nv_bfloat162(h0, h1);
    *(__nv_bfloat162*)(H + i + 2) = __nv_bfloat162(h2, h3);
    *(__nv_bfloat162*)(L + i)     = __nv_bfloat162(l0, l1);
    *(__nv_bfloat162*)(L + i + 2) = __nv_bfloat162(l2, l3);
}

__global__ void convBT(const float* __restrict__ W, __nv_bfloat16* __restrict__ H,
                       __nv_bfloat16* __restrict__ L, int K, int N)
{
    __shared__ float s[32][33];
    int nb = blockIdx.x * 32, kb = blockIdx.y * 32;
    int tx = threadIdx.x, ty = threadIdx.y;
#pragma unroll
    for (int i = 0; i < 4; i++)
        s[ty + i * 8][tx] = W[(size_t)(kb + ty + i * 8) * N + nb + tx];
    __syncthreads();
#pragma unroll
    for (int i = 0; i < 4; i++) {
        float v = s[tx][ty + i * 8];
        __nv_bfloat16 h = __float2bfloat16(v);
        __nv_bfloat16 l = __float2bfloat16(v - __bfloat162float(h));
        size_t o = (size_t)(nb + ty + i * 8) * K + kb + tx;
        H[o] = h; L[o] = l;
    }
}

// ============ bf16 split GEMM on mma.sync (unchanged, validated) ===========
#define MG_STAGE 65536
#define MG_TOTAL (2 * MG_STAGE)

__global__ __launch_bounds__(256, 1)
void mma_gemm(const __nv_bfloat16* __restrict__ Ah, const __nv_bfloat16* __restrict__ Al,
              const __nv_bfloat16* __restrict__ Bh, const __nv_bfloat16* __restrict__ Bl,
              float* __restrict__ C, int M, int N, int K)
{
    extern __shared__ char smem[];
    const uint32_t sb = s2u(smem);
    const int tid = threadIdx.x;
    const int wid = tid >> 5, lane = tid & 31;
    const int bx = blockIdx.x, by = blockIdx.y;
    const int wm = (wid & 3) * 32;
    const int wn = (wid >> 2) * 64;

    const __nv_bfloat16* pAh = Ah + (size_t)(by * 128) * K;
    const __nv_bfloat16* pAl = Al + (size_t)(by * 128) * K;
    const __nv_bfloat16* pBh = Bh + (size_t)(bx * 128) * K;
    const __nv_bfloat16* pBl = Bl + (size_t)(bx * 128) * K;

    const int NC = K >> 6;

    float acc[2][8][4];
#pragma unroll
    for (int mf = 0; mf < 2; mf++)
#pragma unroll
        for (int nf = 0; nf < 8; nf++)
#pragma unroll
            for (int q = 0; q < 4; q++) acc[mf][nf][q] = 0.f;

    auto issue = [&](int ch, int st) {
        uint32_t stb = sb + st * MG_STAGE;
        int k0 = ch << 6;
#pragma unroll
        for (int it = 0; it < 4; it++) {
            int idx = tid + it * 256;
            int row = idx >> 3, c8 = idx & 7;
            uint32_t so = swz(row * 128 + c8 * 16);
            size_t go = (size_t)row * K + k0 + c8 * 8;
            cpa16(stb + 0 * 16384 + so, pAh + go);
            cpa16(stb + 1 * 16384 + so, pAl + go);
            cpa16(stb + 2 * 16384 + so, pBh + go);
            cpa16(stb + 3 * 16384 + so, pBl + go);
        }
        asm volatile("cp.async.commit_group;" ::: "memory");
    };

    issue(0, 0);

    const int a_r  = lane & 15;
    const int a_kb = (lane >> 4) * 16;
    const int b_r  = (lane & 7) + ((lane >> 4) & 1) * 8;
    const int b_kb = ((lane >> 3) & 1) * 16;

    for (int ch = 0; ch < NC; ch++) {
        const int st = ch & 1;
        if (ch + 1 < NC) issue(ch + 1, st ^ 1);
        if (ch + 1 < NC)
            asm volatile("cp.async.wait_group 1;" ::: "memory");
        else
            asm volatile("cp.async.wait_group 0;" ::: "memory");
        __syncthreads();

        const uint32_t sAh = sb + st * MG_STAGE + 0 * 16384;
        const uint32_t sAl = sb + st * MG_STAGE + 1 * 16384;
        const uint32_t sBh = sb + st * MG_STAGE + 2 * 16384;
        const uint32_t sBl = sb + st * MG_STAGE + 3 * 16384;

#pragma unroll
        for (int ks = 0; ks < 4; ks++) {
            uint32_t aH[2][4], aL[2][4], bH[16], bL[16];
#pragma unroll
            for (int mf = 0; mf < 2; mf++) {
                uint32_t off = swz((wm + mf * 16 + a_r) * 128 + ks * 32 + a_kb);
                ldsm4(aH[mf], sAh + off);
                ldsm4(aL[mf], sAl + off);
            }
#pragma unroll
            for (int g = 0; g < 4; g++) {
                uint32_t off = swz((wn + g * 16 + b_r) * 128 + ks * 32 + b_kb);
                ldsm4(bH + g * 4, sBh + off);
                ldsm4(bL + g * 4, sBl + off);
            }
#pragma unroll
            for (int mf = 0; mf < 2; mf++)
#pragma unroll
                for (int nf = 0; nf < 8; nf++) {
                    MMA_BF16(acc[mf][nf], aH[mf], bH + nf * 2);
                    MMA_BF16(acc[mf][nf], aH[mf], bL + nf * 2);
                    MMA_BF16(acc[mf][nf], aL[mf], bH + nf * 2);
                }
        }
        __syncthreads();
    }

    const int er = lane >> 2, ec = (lane & 3) * 2;
#pragma unroll
    for (int mf = 0; mf < 2; mf++) {
#pragma unroll
        for (int nf = 0; nf < 8; nf++) {
            int row0 = by * 128 + wm + mf * 16 + er;
            int col  = bx * 128 + wn + nf * 8 + ec;
            float2 v0 = make_float2(acc[mf][nf][0], acc[mf][nf][1]);
            float2 v1 = make_float2(acc[mf][nf][2], acc[mf][nf][3]);
            *(float2*)(C + (size_t)row0 * N + col)       = v0;
            *(float2*)(C + (size_t)(row0 + 8) * N + col) = v1;
        }
    }
}

// ---------------- RMSNorm -> bf16 hi/lo, head-major relayout ---------------
__global__ void rms_q(const float* __restrict__ qn1, const float* __restrict__ qn2)
{
    int item = blockIdx.x * 8 + (threadIdx.x >> 5);
    int lane = threadIdx.x & 31;
    int half = item & 1;
    int h = (item >> 1) & (HH - 1);
    int t = (item >> 5) & (TT - 1);
    int b = item >> 15;
    const float* src = g_QQ + (size_t)(b * TT + t) * 2048 + half * 1024 + h * 64;
    float v0 = src[lane], v1 = src[lane + 32];
    float ss = v0 * v0 + v1 * v1;
    ss += __shfl_xor_sync(0xffffffffu, ss, 16);
    ss += __shfl_xor_sync(0xffffffffu, ss, 8);
    ss += __shfl_xor_sync(0xffffffffu, ss, 4);
    ss += __shfl_xor_sync(0xffffffffu, ss, 2);
    ss += __shfl_xor_sync(0xffffffffu, ss, 1);
    float inv = rsqrtf(ss * (1.0f / 64.0f) + 1e-5f);
    const float* w = half ? qn2 : qn1;
    float r0 = v0 * inv * w[lane];
    float r1 = v1 * inv * w[lane + 32];
    size_t doff = (size_t)((b * HH + h) * TT + t) * 64;
    __nv_bfloat16* dh = (half ? g_q2h : g_q1h) + doff;
    __nv_bfloat16* dl = (half ? g_q2l : g_q1l) + doff;
    __nv_bfloat16 h0 = __float2bfloat16(r0), h1 = __float2bfloat16(r1);
    dh[lane]      = h0; dl[lane]      = __float2bfloat16(r0 - __bfloat162float(h0));
    dh[lane + 32] = h1; dl[lane + 32] = __float2bfloat16(r1 - __bfloat162float(h1));
}

__global__ void rms_kv(const float* __restrict__ kn1, const float* __restrict__ kn2)
{
    int item = blockIdx.x * 8 + (threadIdx.x >> 5);
    int lane = threadIdx.x & 31;
    int part = item % 3;
    int rest = item / 3;
    int h = rest & (HH - 1);
    int t = (rest >> 4) & (TT - 1);
    int b = rest >> 14;
    const float* src = g_KV + (size_t)(b * TT + t) * 3072 + part * 1024 + h * 64;
    float v0 = src[lane], v1 = src[lane + 32];
    size_t doff = (size_t)((b * HH + h) * TT + t) * 64;
    float r0, r1;
    __nv_bfloat16 *dh, *dl;
    if (part == 2) {
        r0 = v0; r1 = v1;
        dh = g_vh + doff; dl = g_vl + doff;
    } else {
        float ss = v0 * v0 + v1 * v1;
        ss += __shfl_xor_sync(0xffffffffu, ss, 16);
        ss += __shfl_xor_sync(0xffffffffu, ss, 8);
        ss += __shfl_xor_sync(0xffffffffu, ss, 4);
        ss += __shfl_xor_sync(0xffffffffu, ss, 2);
        ss += __shfl_xor_sync(0xffffffffu, ss, 1);
        float inv = rsqrtf(ss * (1.0f / 64.0f) + 1e-5f);
        const float* w = part ? kn2 : kn1;
        r0 = v0 * inv * w[lane];
        r1 = v1 * inv * w[lane + 32];
        dh = (part ? g_k2h : g_k1h) + doff;
        dl = (part ? g_k2l : g_k1l) + doff;
    }
    __nv_bfloat16 h0 = __float2bfloat16(r0), h1 = __float2bfloat16(r1);
    dh[lane]      = h0; dl[lane]      = __float2bfloat16(r0 - __bfloat162float(h0));
    dh[lane + 32] = h1; dl[lane + 32] = __float2bfloat16(r1 - __bfloat162float(h1));
}

// ================= tensor-core differential flash attention ================
// CTA: 128 q-rows x one (b,h). 8 warps x 16 rows. KV chunks of 64 rows,
// double-buffered via cp.async.
// Smem: Q (4 x 16KB) | stage0 (6 x 8KB) | stage1 (6 x 8KB) = 160KB.
#define KVST 49152
#define AT_SMEM (4 * 16384 + 2 * KVST)

__global__ __launch_bounds__(256, 1)
void attn_mma(const float* __restrict__ lmb)
{
    extern __shared__ char smem[];
    const uint32_t sb = s2u(smem);
    const int tid = threadIdx.x;
    const int wid = tid >> 5, lane = tid & 31;
    const int qt = blockIdx.x, h = blockIdx.y, b = blockIdx.z;
    const size_t bh = (size_t)(b * HH + h) * (TT * HD);
    const int wm = wid * 16;
    const uint32_t kv0 = sb + 4 * 16384;

    // ---- Q tiles via cp.async ----
    {
        size_t qoff = bh + (size_t)qt * 128 * 64;
#pragma unroll
        for (int it = 0; it < 4; it++) {
            int idx = tid + it * 256;
            int row = idx >> 3, c8 = idx & 7;
            uint32_t so = swz(row * 128 + c8 * 16);
            size_t g = qoff + (size_t)row * 64 + c8 * 8;
            cpa16(sb + 0 * 16384 + so, g_q1h + g);
            cpa16(sb + 1 * 16384 + so, g_q1l + g);
            cpa16(sb + 2 * 16384 + so, g_q2h + g);
            cpa16(sb + 3 * 16384 + so, g_q2l + g);
        }
        asm volatile("cp.async.commit_group;" ::: "memory");
    }

    auto kvissue = [&](int kt, int st) {
        uint32_t stb = kv0 + st * KVST;
        size_t kbase = bh + (size_t)kt * 64 * 64;
#pragma unroll
        for (int it = 0; it < 2; it++) {
            int idx = tid + it * 256;
            int row = idx >> 3, c8 = idx & 7;
            uint32_t so = swz(row * 128 + c8 * 16);
            size_t g = kbase + (size_t)row * 64 + c8 * 8;
            cpa16(stb + 0 * 8192 + so, g_k1h + g);
            cpa16(stb + 1 * 8192 + so, g_k1l + g);
            cpa16(stb + 2 * 8192 + so, g_k2h + g);
            cpa16(stb + 3 * 8192 + so, g_k2l + g);
            cpa16(stb + 4 * 8192 + so, g_vh + g);
            cpa16(stb + 5 * 8192 + so, g_vl + g);
        }
        asm volatile("cp.async.commit_group;" ::: "memory");
    };

    kvissue(0, 0);

    float o1[8][4], o2[8][4];
#pragma unroll
    for (int d = 0; d < 8; d++)
#pragma unroll
        for (int q = 0; q < 4; q++) { o1[d][q] = 0.f; o2[d][q] = 0.f; }
    float m1[2] = {-1e30f, -1e30f}, l1[2] = {0.f, 0.f};
    float m2[2] = {-1e30f, -1e30f}, l2[2] = {0.f, 0.f};

    const uint32_t a_off = (wm + (lane & 15)) * 128 + (lane >> 4) * 16;
    const uint32_t b_off = ((lane & 7) + ((lane >> 4) & 1) * 8) * 128
                         + ((lane >> 3) & 1) * 16;
    const uint32_t v_off = (lane & 15) * 128 + (lane >> 4) * 16;

    for (int kt = 0; kt < 16; kt++) {
        const int st = kt & 1;
        if (kt + 1 < 16) kvissue(kt + 1, st ^ 1);
        if (kt + 1 < 16)
            asm volatile("cp.async.wait_group 1;" ::: "memory");
        else
            asm volatile("cp.async.wait_group 0;" ::: "memory");
        __syncthreads();

        const uint32_t stb = kv0 + st * KVST;

#pragma unroll
        for (int br = 0; br < 2; br++) {
            const uint32_t sAh = sb + (br ? 2 : 0) * 16384;
            const uint32_t sAl = sAh + 16384;
            const uint32_t sBh = stb + (br ? 2 : 0) * 8192;
            const uint32_t sBl = sBh + 8192;
            float* m = br ? m2 : m1;
            float* l = br ? l2 : l1;
            float (*o)[4] = br ? o2 : o1;

            // ---- S = Q K^T over 64 keys (3-product split) ----
            float sf[8][4];
#pragma unroll
            for (int nf = 0; nf < 8; nf++)
#pragma unroll
                for (int q = 0; q < 4; q++) sf[nf][q] = 0.f;
#pragma unroll
            for (int ks = 0; ks < 4; ks++) {
                uint32_t aH[4], aL[4];
                ldsm4(aH, sAh + swz(a_off + ks * 32));
                ldsm4(aL, sAl + swz(a_off + ks * 32));
#pragma unroll
                for (int g = 0; g < 4; g++) {
                    uint32_t bH[4], bL[4];
                    uint32_t off = swz(b_off + g * 2048 + ks * 32);
                    ldsm4(bH, sBh + off);
                    ldsm4(bL, sBl + off);
                    MMA_BF16(sf[2*g],   aH, bH);
                    MMA_BF16(sf[2*g],   aH, bL);
                    MMA_BF16(sf[2*g],   aL, bH);
                    MMA_BF16(sf[2*g+1], aH, bH + 2);
                    MMA_BF16(sf[2*g+1], aH, bL + 2);
                    MMA_BF16(sf[2*g+1], aL, bH + 2);
                }
            }

            // ---- online softmax (rows r0 = lane>>2, r1 = r0+8) ----
            float mx0 = -1e30f, mx1 = -1e30f;
#pragma unroll
            for (int nf = 0; nf < 8; nf++) {
                sf[nf][0] *= 0.125f; sf[nf][1] *= 0.125f;
                sf[nf][2] *= 0.125f; sf[nf][3] *= 0.125f;
                mx0 = fmaxf(mx0, fmaxf(sf[nf][0], sf[nf][1]));
                mx1 = fmaxf(mx1, fmaxf(sf[nf][2], sf[nf][3]));
            }
            mx0 = fmaxf(mx0, __shfl_xor_sync(0xffffffffu, mx0, 1));
            mx0 = fmaxf(mx0, __shfl_xor_sync(0xffffffffu, mx0, 2));
            mx1 = fmaxf(mx1, __shfl_xor_sync(0xffffffffu, mx1, 1));
            mx1 = fmaxf(mx1, __shfl_xor_sync(0xffffffffu, mx1, 2));
            float mn0 = fmaxf(m[0], mx0), mn1 = fmaxf(m[1], mx1);
            float al0 = __expf(m[0] - mn0), al1 = __expf(m[1] - mn1);
            float ls0 = 0.f, ls1 = 0.f;
#pragma unroll
            for (int nf = 0; nf < 8; nf++) {
                sf[nf][0] = __expf(sf[nf][0] - mn0); ls0 += sf[nf][0];
                sf[nf][1] = __expf(sf[nf][1] - mn0); ls0 += sf[nf][1];
                sf[nf][2] = __expf(sf[nf][2] - mn1); ls1 += sf[nf][2];
                sf[nf][3] = __expf(sf[nf][3] - mn1); ls1 += sf[nf][3];
            }
            ls0 += __shfl_xor_sync(0xffffffffu, ls0, 1);
            ls0 += __shfl_xor_sync(0xffffffffu, ls0, 2);
            ls1 += __shfl_xor_sync(0xffffffffu, ls1, 1);
            ls1 += __shfl_xor_sync(0xffffffffu, ls1, 2);
            l[0] = l[0] * al0 + ls0; m[0] = mn0;
            l[1] = l[1] * al1 + ls1; m[1] = mn1;
#pragma unroll
            for (int d = 0; d < 8; d++) {
                o[d][0] *= al0; o[d][1] *= al0;
                o[d][2] *= al1; o[d][3] *= al1;
            }

            // ---- P -> packed bf16 hi/lo fragments (A-layout) ----
            uint32_t ph[4][4], pl[4][4];
#pragma unroll
            for (int kf = 0; kf < 4; kf++) {
                float* f0 = sf[2*kf];
                float* f1 = sf[2*kf+1];
                ph[kf][0] = pkhi(f0[0], f0[1]);
                ph[kf][1] = pkhi(f0[2], f0[3]);
                ph[kf][2] = pkhi(f1[0], f1[1]);
                ph[kf][3] = pkhi(f1[2], f1[3]);
                pl[kf][0] = pkbf2(trunclo(f0[0]), trunclo(f0[1]));
                pl[kf][1] = pkbf2(trunclo(f0[2]), trunclo(f0[3]));
                pl[kf][2] = pkbf2(trunclo(f1[0]), trunclo(f1[1]));
                pl[kf][3] = pkbf2(trunclo(f1[2]), trunclo(f1[3]));
            }

            // ---- O += P V (3-product split) ----
            const uint32_t sVh = stb + 4 * 8192;
            const uint32_t sVl = stb + 5 * 8192;
#pragma unroll
            for (int kf = 0; kf < 4; kf++) {
#pragma unroll
                for (int d2 = 0; d2 < 4; d2++) {
                    uint32_t vH[4], vL[4];
                    uint32_t off = swz(v_off + kf * 2048 + d2 * 32);
                    ldsm4t(vH, sVh + off);
                    ldsm4t(vL, sVl + off);
                    MMA_BF16(o[d2*2],   ph[kf], vH);
                    MMA_BF16(o[d2*2],   ph[kf], vL);
                    MMA_BF16(o[d2*2],   pl[kf], vH);
                    MMA_BF16(o[d2*2+1], ph[kf], vH + 2);
                    MMA_BF16(o[d2*2+1], ph[kf], vL + 2);
                    MMA_BF16(o[d2*2+1], pl[kf], vH + 2);
                }
            }
        }
    }

    // ---- epilogue: y = O1/l1 - softplus(lmb)·O2/l2 ----
    float cH = log1pf(__expf(lmb[h]));
    float i10 = 1.f / l1[0], i11 = 1.f / l1[1];
    float i20 = 1.f / l2[0], i21 = 1.f / l2[1];
    const int er = lane >> 2, ec = (lane & 3) * 2;
#pragma unroll
    for (int d = 0; d < 8; d++) {
        size_t r0 = bh + (size_t)(qt * 128 + wm + er) * 64 + d * 8 + ec;
        size_t r1 = r0 + 8 * 64;
        float2 v0 = make_float2(o1[d][0] * i10 - cH * o2[d][0] * i20,
                                o1[d][1] * i10 - cH * o2[d][1] * i20);
        float2 v1 = make_float2(o1[d][2] * i11 - cH * o2[d][2] * i21,
                                o1[d][3] * i11 - cH * o2[d][3] * i21);
        *(float2*)(g_y + r0) = v0;
        *(float2*)(g_y + r1) = v1;
    }
}

// ---------------- GroupNorm per (b,h) over (T, HD), then relayout ----------
__global__ void groupnorm_kernel(const float* __restrict__ gn_w,
                                 const float* __restrict__ gn_b)
{
    __shared__ float rs[256], rq[256];
    const int bh = blockIdx.x;
    const float* src = g_y + (size_t)bh * TT * HD;
    const int tid = threadIdx.x;
    float s = 0.f, sq = 0.f;
    for (int i = tid; i < TT * HD; i += 256) {
        float v = src[i]; s += v; sq += v * v;
    }
    rs[tid] = s; rq[tid] = sq;
    __syncthreads();
    for (int off = 128; off > 0; off >>= 1) {
        if (tid < off) { rs[tid] += rs[tid + off]; rq[tid] += rq[tid + off]; }
        __syncthreads();
    }
    float mu  = rs[0] * (1.f / 65536.f);
    float var = rq[0] * (1.f / 65536.f) - mu * mu;
    float inv = rsqrtf(var + 1e-5f);
    int b = bh >> 4, h = bh & 15;
    for (int i = tid; i < TT * HD; i += 256) {
        int t = i >> 6, d = i & 63;
        float v = (src[i] - mu) * inv;
        g_yt[(size_t)(b * TT + t) * DD + h * 64 + d] =
            v * gn_w[h * 64 + d] + gn_b[h * 64 + d];
    }
}

// ---------------------------------------------------------------------------
extern "C" void kernel_launch(void* const* d_in, const int* in_sizes, int n_in,
                              void* d_out, int out_size)
{
    const float* x_q  = (const float*)d_in[0];
    const float* x_kv = (const float*)d_in[1];
    const float* Wq   = (const float*)d_in[2];
    const float* Wkv  = (const float*)d_in[3];
    const float* Wc   = (const float*)d_in[4];
    const float* qn1  = (const float*)d_in[5];
    const float* kn1  = (const float*)d_in[6];
    const float* qn2  = (const float*)d_in[7];
    const float* kn2  = (const float*)d_in[8];
    const float* gn_w = (const float*)d_in[9];
    const float* gn_b = (const float*)d_in[10];
    const float* lmb  = (const float*)d_in[11];
    float* out = (float*)d_out;
    (void)in_sizes; (void)n_in; (void)out_size;

    float *QQ, *KV, *YT;
    __nv_bfloat16 *AH, *AL, *BH, *BL;
    cudaGetSymbolAddress((void**)&QQ, g_QQ);
    cudaGetSymbolAddress((void**)&KV, g_KV);
    cudaGetSymbolAddress((void**)&YT, g_yt);
    cudaGetSymbolAddress((void**)&AH, g_AH);
    cudaGetSymbolAddress((void**)&AL, g_AL);
    cudaGetSymbolAddress((void**)&BH, g_BH);
    cudaGetSymbolAddress((void**)&BL, g_BL);

    cudaFuncSetAttribute(mma_gemm,
        cudaFuncAttributeMaxDynamicSharedMemorySize, MG_TOTAL);
    cudaFuncSetAttribute(attn_mma,
        cudaFuncAttributeMaxDynamicSharedMemorySize, AT_SMEM);

    // 1) QQ = x_q @ Wq
    convA<<<4096, 256>>>(x_q, AH, AL);
    convBT<<<dim3(64, 32), dim3(32, 8)>>>(Wq, BH, BL, 1024, 2048);
    mma_gemm<<<dim3(16, 32), 256, MG_TOTAL>>>(AH, AL, BH, BL, QQ, 4096, 2048, 1024);
    // 2) KV = x_kv @ Wkv
    convA<<<4096, 256>>>(x_kv, AH, AL);
    convBT<<<dim3(96, 32), dim3(32, 8)>>>(Wkv, BH, BL, 1024, 3072);
    mma_gemm<<<dim3(24, 32), 256, MG_TOTAL>>>(AH, AL, BH, BL, KV, 4096, 3072, 1024);
    // 3) per-head RMSNorm -> bf16 hi/lo, head-major
    rms_q <<<16384, 256>>>(qn1, qn2);
    rms_kv<<<24576, 256>>>(kn1, kn2);
    // 4) tensor-core differential flash attention (double-buffered)
    attn_mma<<<dim3(8, 16, 4), 256, AT_SMEM>>>(lmb);
    // 5) GroupNorm + relayout
    groupnorm_kernel<<<64, 256>>>(gn_w, gn_b);
    // 6) out = yt @ Wc
    convA<<<4096, 256>>>(YT, AH, AL);
    convBT<<<dim3(32, 32), dim3(32, 8)>>>(Wc, BH, BL, 1024, 1024);
    mma_gemm<<<dim3(8, 32), 256, MG_TOTAL>>>(AH, AL, BH, BL, out, 4096, 1024, 1024);
}

// round 11
// speedup vs baseline: 8.6412x; 1.0859x over previous
#include <cuda_runtime.h>
#include <cuda_bf16.h>
#include <math.h>
#include <stdint.h>

#define BB 4
#define TT 1024
#define DD 1024
#define HH 16
#define HD 64

// softmax scale folded into Q: log2(e)/8
#define QSCALE 0.18033688011112042f

typedef unsigned long long ull;

// ---------------- scratch (device globals; no allocation allowed) ----------
__device__ float g_QQ[BB*TT*2*DD];     // x_q @ Wq   (B,T,2048)
__device__ float g_KV[BB*TT*3*DD];     // x_kv @ Wkv (B,T,3072)
__device__ float g_y [BB*HH*TT*HD];    // attention out (B,H,T,64) fp32
// bf16 split operands for the projection GEMMs
__device__ __nv_bfloat16 g_AH[4096*1024];
__device__ __nv_bfloat16 g_AL[4096*1024];
__device__ __nv_bfloat16 g_BH[3072*1024];   // transposed: [N,K]
__device__ __nv_bfloat16 g_BL[3072*1024];
// bf16 hi/lo attention operands, (B,H,T,64)
#define AELE (BB*HH*TT*HD)
__device__ __nv_bfloat16 g_q1h[AELE], g_q1l[AELE], g_q2h[AELE], g_q2l[AELE];
__device__ __nv_bfloat16 g_k1h[AELE], g_k1l[AELE], g_k2h[AELE], g_k2l[AELE];
__device__ __nv_bfloat16 g_vh [AELE], g_vl [AELE];

// =================== small asm helpers =====================================
__device__ __forceinline__ uint32_t s2u(const void* p) {
    uint32_t a;
    asm("{ .reg .u64 t; cvta.to.shared.u64 t, %1; cvt.u32.u64 %0, t; }" : "=r"(a) : "l"(p));
    return a;
}
__device__ __forceinline__ void cpa16(uint32_t d, const void* s) {
    asm volatile("cp.async.cg.shared.global [%0], [%1], 16;" :: "r"(d), "l"(s));
}
__device__ __forceinline__ void ldsm4(uint32_t* r, uint32_t a) {
    asm volatile("ldmatrix.sync.aligned.m8n8.x4.shared.b16 {%0,%1,%2,%3}, [%4];"
                 : "=r"(r[0]), "=r"(r[1]), "=r"(r[2]), "=r"(r[3]) : "r"(a));
}
__device__ __forceinline__ void ldsm4t(uint32_t* r, uint32_t a) {
    asm volatile("ldmatrix.sync.aligned.m8n8.x4.trans.shared.b16 {%0,%1,%2,%3}, [%4];"
                 : "=r"(r[0]), "=r"(r[1]), "=r"(r[2]), "=r"(r[3]) : "r"(a));
}
#define MMA_BF16(d, a, b)                                                     \
    asm volatile("mma.sync.aligned.m16n8k16.row.col.f32.bf16.bf16.f32 "       \
        "{%0,%1,%2,%3}, {%4,%5,%6,%7}, {%8,%9}, {%0,%1,%2,%3};"               \
        : "+f"((d)[0]), "+f"((d)[1]), "+f"((d)[2]), "+f"((d)[3])              \
        : "r"((a)[0]), "r"((a)[1]), "r"((a)[2]), "r"((a)[3]),                 \
          "r"((b)[0]), "r"((b)[1]))
__device__ __forceinline__ uint32_t swz(uint32_t bo) {
    return bo ^ ((bo >> 3) & 0x70);
}
__device__ __forceinline__ uint32_t pkhi(float a, float b) {
    uint32_t d;
    asm("prmt.b32 %0, %1, %2, 0x7632;" : "=r"(d)
        : "r"(__float_as_uint(a)), "r"(__float_as_uint(b)));
    return d;
}
__device__ __forceinline__ uint32_t pkbf2(float lo, float hi) {
    uint32_t d;
    asm("cvt.rn.bf16x2.f32 %0, %1, %2;" : "=r"(d) : "f"(hi), "f"(lo));
    return d;
}
__device__ __forceinline__ float trunclo(float f) {
    return f - __uint_as_float(__float_as_uint(f) & 0xFFFF0000u);
}
__device__ __forceinline__ float ex2(float x) {
    float y;
    asm("ex2.approx.f32 %0, %1;" : "=f"(y) : "f"(x));
    return y;
}

// =================== fp32 -> bf16 hi/lo split kernels ======================
__global__ void convA(const float* __restrict__ X, __nv_bfloat16* __restrict__ H,
                      __nv_bfloat16* __restrict__ L)
{
    int i = (blockIdx.x * 256 + threadIdx.x) * 4;
    float4 v = *(const float4*)(X + i);
    __nv_bfloat16 h0 = __float2bfloat16(v.x), h1 = __float2bfloat16(v.y);
    __nv_bfloat16 h2 = __float2bfloat16(v.z), h3 = __float2bfloat16(v.w);
    __nv_bfloat16 l0 = __float2bfloat16(v.x - __bfloat162float(h0));
    __nv_bfloat16 l1 = __float2bfloat16(v.y - __bfloat162float(h1));
    __nv_bfloat16 l2 = __float2bfloat16(v.z - __bfloat162float(h2));
    __nv_bfloat16 l3 = __float2bfloat16(v.w - __bfloat162float(h3));
    *(__nv_bfloat162*)(H + i)     = __nv_bfloat162(h0, h1);
    *(__nv_bfloat162*)(H + i + 2) = __nv_bfloat162(h2, h3);
    *(__nv_bfloat162*)(L + i)     = __nv_bfloat162(l0, l1);
    *(__nv_bfloat162*)(L + i + 2) = __nv_bfloat162(l2, l3);
}

__global__ void convBT(const float* __restrict__ W, __nv_bfloat16* __restrict__ H,
                       __nv_bfloat16* __restrict__ L, int K, int N)
{
    __shared__ float s[32][33];
    int nb = blockIdx.x * 32, kb = blockIdx.y * 32;
    int tx = threadIdx.x, ty = threadIdx.y;
#pragma unroll
    for (int i = 0; i < 4; i++)
        s[ty + i * 8][tx] = W[(size_t)(kb + ty + i * 8) * N + nb + tx];
    __syncthreads();
#pragma unroll
    for (int i = 0; i < 4; i++) {
        float v = s[tx][ty + i * 8];
        __nv_bfloat16 h = __float2bfloat16(v);
        __nv_bfloat16 l = __float2bfloat16(v - __bfloat162float(h));
        size_t o = (size_t)(nb + ty + i * 8) * K + kb + tx;
        H[o] = h; L[o] = l;
    }
}

// ============ bf16 split GEMM on mma.sync (unchanged, validated) ===========
#define MG_STAGE 65536
#define MG_TOTAL (2 * MG_STAGE)

__global__ __launch_bounds__(256, 1)
void mma_gemm(const __nv_bfloat16* __restrict__ Ah, const __nv_bfloat16* __restrict__ Al,
              const __nv_bfloat16* __restrict__ Bh, const __nv_bfloat16* __restrict__ Bl,
              float* __restrict__ C, int M, int N, int K)
{
    extern __shared__ char smem[];
    const uint32_t sb = s2u(smem);
    const int tid = threadIdx.x;
    const int wid = tid >> 5, lane = tid & 31;
    const int bx = blockIdx.x, by = blockIdx.y;
    const int wm = (wid & 3) * 32;
    const int wn = (wid >> 2) * 64;

    const __nv_bfloat16* pAh = Ah + (size_t)(by * 128) * K;
    const __nv_bfloat16* pAl = Al + (size_t)(by * 128) * K;
    const __nv_bfloat16* pBh = Bh + (size_t)(bx * 128) * K;
    const __nv_bfloat16* pBl = Bl + (size_t)(bx * 128) * K;

    const int NC = K >> 6;

    float acc[2][8][4];
#pragma unroll
    for (int mf = 0; mf < 2; mf++)
#pragma unroll
        for (int nf = 0; nf < 8; nf++)
#pragma unroll
            for (int q = 0; q < 4; q++) acc[mf][nf][q] = 0.f;

    auto issue = [&](int ch, int st) {
        uint32_t stb = sb + st * MG_STAGE;
        int k0 = ch << 6;
#pragma unroll
        for (int it = 0; it < 4; it++) {
            int idx = tid + it * 256;
            int row = idx >> 3, c8 = idx & 7;
            uint32_t so = swz(row * 128 + c8 * 16);
            size_t go = (size_t)row * K + k0 + c8 * 8;
            cpa16(stb + 0 * 16384 + so, pAh + go);
            cpa16(stb + 1 * 16384 + so, pAl + go);
            cpa16(stb + 2 * 16384 + so, pBh + go);
            cpa16(stb + 3 * 16384 + so, pBl + go);
        }
        asm volatile("cp.async.commit_group;" ::: "memory");
    };

    issue(0, 0);

    const int a_r  = lane & 15;
    const int a_kb = (lane >> 4) * 16;
    const int b_r  = (lane & 7) + ((lane >> 4) & 1) * 8;
    const int b_kb = ((lane >> 3) & 1) * 16;

    for (int ch = 0; ch < NC; ch++) {
        const int st = ch & 1;
        if (ch + 1 < NC) issue(ch + 1, st ^ 1);
        if (ch + 1 < NC)
            asm volatile("cp.async.wait_group 1;" ::: "memory");
        else
            asm volatile("cp.async.wait_group 0;" ::: "memory");
        __syncthreads();

        const uint32_t sAh = sb + st * MG_STAGE + 0 * 16384;
        const uint32_t sAl = sb + st * MG_STAGE + 1 * 16384;
        const uint32_t sBh = sb + st * MG_STAGE + 2 * 16384;
        const uint32_t sBl = sb + st * MG_STAGE + 3 * 16384;

#pragma unroll
        for (int ks = 0; ks < 4; ks++) {
            uint32_t aH[2][4], aL[2][4], bH[16], bL[16];
#pragma unroll
            for (int mf = 0; mf < 2; mf++) {
                uint32_t off = swz((wm + mf * 16 + a_r) * 128 + ks * 32 + a_kb);
                ldsm4(aH[mf], sAh + off);
                ldsm4(aL[mf], sAl + off);
            }
#pragma unroll
            for (int g = 0; g < 4; g++) {
                uint32_t off = swz((wn + g * 16 + b_r) * 128 + ks * 32 + b_kb);
                ldsm4(bH + g * 4, sBh + off);
                ldsm4(bL + g * 4, sBl + off);
            }
#pragma unroll
            for (int mf = 0; mf < 2; mf++)
#pragma unroll
                for (int nf = 0; nf < 8; nf++) {
                    MMA_BF16(acc[mf][nf], aH[mf], bH + nf * 2);
                    MMA_BF16(acc[mf][nf], aH[mf], bL + nf * 2);
                    MMA_BF16(acc[mf][nf], aL[mf], bH + nf * 2);
                }
        }
        __syncthreads();
    }

    const int er = lane >> 2, ec = (lane & 3) * 2;
#pragma unroll
    for (int mf = 0; mf < 2; mf++) {
#pragma unroll
        for (int nf = 0; nf < 8; nf++) {
            int row0 = by * 128 + wm + mf * 16 + er;
            int col  = bx * 128 + wn + nf * 8 + ec;
            float2 v0 = make_float2(acc[mf][nf][0], acc[mf][nf][1]);
            float2 v1 = make_float2(acc[mf][nf][2], acc[mf][nf][3]);
            *(float2*)(C + (size_t)row0 * N + col)       = v0;
            *(float2*)(C + (size_t)(row0 + 8) * N + col) = v1;
        }
    }
}

// ---------------- RMSNorm -> bf16 hi/lo, head-major relayout ---------------
// Q additionally pre-scaled by log2(e)/8 so softmax is a bare ex2.
__global__ void rms_q(const float* __restrict__ qn1, const float* __restrict__ qn2)
{
    int item = blockIdx.x * 8 + (threadIdx.x >> 5);
    int lane = threadIdx.x & 31;
    int half = item & 1;
    int h = (item >> 1) & (HH - 1);
    int t = (item >> 5) & (TT - 1);
    int b = item >> 15;
    const float* src = g_QQ + (size_t)(b * TT + t) * 2048 + half * 1024 + h * 64;
    float v0 = src[lane], v1 = src[lane + 32];
    float ss = v0 * v0 + v1 * v1;
    ss += __shfl_xor_sync(0xffffffffu, ss, 16);
    ss += __shfl_xor_sync(0xffffffffu, ss, 8);
    ss += __shfl_xor_sync(0xffffffffu, ss, 4);
    ss += __shfl_xor_sync(0xffffffffu, ss, 2);
    ss += __shfl_xor_sync(0xffffffffu, ss, 1);
    float inv = rsqrtf(ss * (1.0f / 64.0f) + 1e-5f) * QSCALE;
    const float* w = half ? qn2 : qn1;
    float r0 = v0 * inv * w[lane];
    float r1 = v1 * inv * w[lane + 32];
    size_t doff = (size_t)((b * HH + h) * TT + t) * 64;
    __nv_bfloat16* dh = (half ? g_q2h : g_q1h) + doff;
    __nv_bfloat16* dl = (half ? g_q2l : g_q1l) + doff;
    __nv_bfloat16 h0 = __float2bfloat16(r0), h1 = __float2bfloat16(r1);
    dh[lane]      = h0; dl[lane]      = __float2bfloat16(r0 - __bfloat162float(h0));
    dh[lane + 32] = h1; dl[lane + 32] = __float2bfloat16(r1 - __bfloat162float(h1));
}

__global__ void rms_kv(const float* __restrict__ kn1, const float* __restrict__ kn2)
{
    int item = blockIdx.x * 8 + (threadIdx.x >> 5);
    int lane = threadIdx.x & 31;
    int part = item % 3;
    int rest = item / 3;
    int h = rest & (HH - 1);
    int t = (rest >> 4) & (TT - 1);
    int b = rest >> 14;
    const float* src = g_KV + (size_t)(b * TT + t) * 3072 + part * 1024 + h * 64;
    float v0 = src[lane], v1 = src[lane + 32];
    size_t doff = (size_t)((b * HH + h) * TT + t) * 64;
    float r0, r1;
    __nv_bfloat16 *dh, *dl;
    if (part == 2) {
        r0 = v0; r1 = v1;
        dh = g_vh + doff; dl = g_vl + doff;
    } else {
        float ss = v0 * v0 + v1 * v1;
        ss += __shfl_xor_sync(0xffffffffu, ss, 16);
        ss += __shfl_xor_sync(0xffffffffu, ss, 8);
        ss += __shfl_xor_sync(0xffffffffu, ss, 4);
        ss += __shfl_xor_sync(0xffffffffu, ss, 2);
        ss += __shfl_xor_sync(0xffffffffu, ss, 1);
        float inv = rsqrtf(ss * (1.0f / 64.0f) + 1e-5f);
        const float* w = part ? kn2 : kn1;
        r0 = v0 * inv * w[lane];
        r1 = v1 * inv * w[lane + 32];
        dh = (part ? g_k2h : g_k1h) + doff;
        dl = (part ? g_k2l : g_k1l) + doff;
    }
    __nv_bfloat16 h0 = __float2bfloat16(r0), h1 = __float2bfloat16(r1);
    dh[lane]      = h0; dl[lane]      = __float2bfloat16(r0 - __bfloat162float(h0));
    dh[lane + 32] = h1; dl[lane + 32] = __float2bfloat16(r1 - __bfloat162float(h1));
}

// ================= tensor-core differential flash attention ================
// CTA: 128 q-rows x one (b,h). 8 warps x 16 rows. KV chunks of 64 rows,
// double-buffered. No online max (|s/8| <= 8 bound); P = 2^(q·k·log2e/8).
// NOTE: trailing __syncthreads() in the chunk loop is LOAD-BEARING — it keeps
// the next iteration's cp.async prefetch from overwriting a stage other warps
// are still reading (post-timing divergence in R7 without it).
#define KVST 49152
#define AT_SMEM (4 * 16384 + 2 * KVST)

__global__ __launch_bounds__(256, 1)
void attn_mma(const float* __restrict__ lmb)
{
    extern __shared__ char smem[];
    const uint32_t sb = s2u(smem);
    const int tid = threadIdx.x;
    const int wid = tid >> 5, lane = tid & 31;
    const int qt = blockIdx.x, h = blockIdx.y, b = blockIdx.z;
    const size_t bh = (size_t)(b * HH + h) * (TT * HD);
    const int wm = wid * 16;
    const uint32_t kv0 = sb + 4 * 16384;

    // ---- Q tiles via cp.async ----
    {
        size_t qoff = bh + (size_t)qt * 128 * 64;
#pragma unroll
        for (int it = 0; it < 4; it++) {
            int idx = tid + it * 256;
            int row = idx >> 3, c8 = idx & 7;
            uint32_t so = swz(row * 128 + c8 * 16);
            size_t g = qoff + (size_t)row * 64 + c8 * 8;
            cpa16(sb + 0 * 16384 + so, g_q1h + g);
            cpa16(sb + 1 * 16384 + so, g_q1l + g);
            cpa16(sb + 2 * 16384 + so, g_q2h + g);
            cpa16(sb + 3 * 16384 + so, g_q2l + g);
        }
        asm volatile("cp.async.commit_group;" ::: "memory");
    }

    auto kvissue = [&](int kt, int st) {
        uint32_t stb = kv0 + st * KVST;
        size_t kbase = bh + (size_t)kt * 64 * 64;
#pragma unroll
        for (int it = 0; it < 2; it++) {
            int idx = tid + it * 256;
            int row = idx >> 3, c8 = idx & 7;
            uint32_t so = swz(row * 128 + c8 * 16);
            size_t g = kbase + (size_t)row * 64 + c8 * 8;
            cpa16(stb + 0 * 8192 + so, g_k1h + g);
            cpa16(stb + 1 * 8192 + so, g_k1l + g);
            cpa16(stb + 2 * 8192 + so, g_k2h + g);
            cpa16(stb + 3 * 8192 + so, g_k2l + g);
            cpa16(stb + 4 * 8192 + so, g_vh + g);
            cpa16(stb + 5 * 8192 + so, g_vl + g);
        }
        asm volatile("cp.async.commit_group;" ::: "memory");
    };

    kvissue(0, 0);

    float o1[8][4], o2[8][4];
#pragma unroll
    for (int d = 0; d < 8; d++)
#pragma unroll
        for (int q = 0; q < 4; q++) { o1[d][q] = 0.f; o2[d][q] = 0.f; }
    float l1[2] = {0.f, 0.f}, l2[2] = {0.f, 0.f};   // per-thread partials

    const uint32_t a_off = (wm + (lane & 15)) * 128 + (lane >> 4) * 16;
    const uint32_t b_off = ((lane & 7) + ((lane >> 4) & 1) * 8) * 128
                         + ((lane >> 3) & 1) * 16;
    const uint32_t v_off = (lane & 15) * 128 + (lane >> 4) * 16;

    for (int kt = 0; kt < 16; kt++) {
        const int st = kt & 1;
        if (kt + 1 < 16) kvissue(kt + 1, st ^ 1);
        if (kt + 1 < 16)
            asm volatile("cp.async.wait_group 1;" ::: "memory");
        else
            asm volatile("cp.async.wait_group 0;" ::: "memory");
        __syncthreads();

        const uint32_t stb = kv0 + st * KVST;

        uint32_t ph1[4][4], pl1[4][4], ph2[4][4], pl2[4][4];

#pragma unroll
        for (int br = 0; br < 2; br++) {
            const uint32_t sAh = sb + (br ? 2 : 0) * 16384;
            const uint32_t sAl = sAh + 16384;
            const uint32_t sBh = stb + (br ? 2 : 0) * 8192;
            const uint32_t sBl = sBh + 8192;
            float* l = br ? l2 : l1;

            // ---- S = Q K^T over 64 keys (3-product split) ----
            float sf[8][4];
#pragma unroll
            for (int nf = 0; nf < 8; nf++)
#pragma unroll
                for (int q = 0; q < 4; q++) sf[nf][q] = 0.f;
#pragma unroll
            for (int ks = 0; ks < 4; ks++) {
                uint32_t aH[4], aL[4];
                ldsm4(aH, sAh + swz(a_off + ks * 32));
                ldsm4(aL, sAl + swz(a_off + ks * 32));
#pragma unroll
                for (int g = 0; g < 4; g++) {
                    uint32_t bH[4], bL[4];
                    uint32_t off = swz(b_off + g * 2048 + ks * 32);
                    ldsm4(bH, sBh + off);
                    ldsm4(bL, sBl + off);
                    MMA_BF16(sf[2*g],   aH, bH);
                    MMA_BF16(sf[2*g],   aH, bL);
                    MMA_BF16(sf[2*g],   aL, bH);
                    MMA_BF16(sf[2*g+1], aH, bH + 2);
                    MMA_BF16(sf[2*g+1], aH, bL + 2);
                    MMA_BF16(sf[2*g+1], aL, bH + 2);
                }
            }

            // ---- P = 2^S ; accumulate per-thread l partials ----
            float p0 = 0.f, p1 = 0.f;
#pragma unroll
            for (int nf = 0; nf < 8; nf++) {
                sf[nf][0] = ex2(sf[nf][0]); p0 += sf[nf][0];
                sf[nf][1] = ex2(sf[nf][1]); p0 += sf[nf][1];
                sf[nf][2] = ex2(sf[nf][2]); p1 += sf[nf][2];
                sf[nf][3] = ex2(sf[nf][3]); p1 += sf[nf][3];
            }
            l[0] += p0; l[1] += p1;

            // ---- pack P fragments (bf16 hi/lo, A-layout) ----
            uint32_t (*ph)[4] = br ? ph2 : ph1;
            uint32_t (*pl)[4] = br ? pl2 : pl1;
#pragma unroll
            for (int kf = 0; kf < 4; kf++) {
                float* f0 = sf[2*kf];
                float* f1 = sf[2*kf+1];
                ph[kf][0] = pkhi(f0[0], f0[1]);
                ph[kf][1] = pkhi(f0[2], f0[3]);
                ph[kf][2] = pkhi(f1[0], f1[1]);
                ph[kf][3] = pkhi(f1[2], f1[3]);
                pl[kf][0] = pkbf2(trunclo(f0[0]), trunclo(f0[1]));
                pl[kf][1] = pkbf2(trunclo(f0[2]), trunclo(f0[3]));
                pl[kf][2] = pkbf2(trunclo(f1[0]), trunclo(f1[1]));
                pl[kf][3] = pkbf2(trunclo(f1[2]), trunclo(f1[3]));
            }
        }

        // ---- O += P V for both branches, V fragments loaded once ----
        const uint32_t sVh = stb + 4 * 8192;
        const uint32_t sVl = stb + 5 * 8192;
#pragma unroll
        for (int kf = 0; kf < 4; kf++) {
#pragma unroll
            for (int d2 = 0; d2 < 4; d2++) {
                uint32_t vH[4], vL[4];
                uint32_t off = swz(v_off + kf * 2048 + d2 * 32);
                ldsm4t(vH, sVh + off);
                ldsm4t(vL, sVl + off);
                MMA_BF16(o1[d2*2],   ph1[kf], vH);
                MMA_BF16(o1[d2*2],   ph1[kf], vL);
                MMA_BF16(o1[d2*2],   pl1[kf], vH);
                MMA_BF16(o1[d2*2+1], ph1[kf], vH + 2);
                MMA_BF16(o1[d2*2+1], ph1[kf], vL + 2);
                MMA_BF16(o1[d2*2+1], pl1[kf], vH + 2);
                MMA_BF16(o2[d2*2],   ph2[kf], vH);
                MMA_BF16(o2[d2*2],   ph2[kf], vL);
                MMA_BF16(o2[d2*2],   pl2[kf], vH);
                MMA_BF16(o2[d2*2+1], ph2[kf], vH + 2);
                MMA_BF16(o2[d2*2+1], ph2[kf], vL + 2);
                MMA_BF16(o2[d2*2+1], pl2[kf], vH + 2);
            }
        }

        __syncthreads();   // all warps done with stage st before it is refilled
    }

    // ---- reduce l across quads (columns of each row) ----
#pragma unroll
    for (int off = 1; off <= 2; off <<= 1) {
        l1[0] += __shfl_xor_sync(0xffffffffu, l1[0], off);
        l1[1] += __shfl_xor_sync(0xffffffffu, l1[1], off);
        l2[0] += __shfl_xor_sync(0xffffffffu, l2[0], off);
        l2[1] += __shfl_xor_sync(0xffffffffu, l2[1], off);
    }

    // ---- epilogue: y = O1/l1 - softplus(lmb)·O2/l2 ----
    float cH = log1pf(__expf(lmb[h]));
    float i10 = 1.f / l1[0], i11 = 1.f / l1[1];
    float i20 = cH / l2[0],  i21 = cH / l2[1];
    const int er = lane >> 2, ec = (lane & 3) * 2;
#pragma unroll
    for (int d = 0; d < 8; d++) {
        size_t r0 = bh + (size_t)(qt * 128 + wm + er) * 64 + d * 8 + ec;
        size_t r1 = r0 + 8 * 64;
        float2 v0 = make_float2(o1[d][0] * i10 - o2[d][0] * i20,
                                o1[d][1] * i10 - o2[d][1] * i20);
        float2 v1 = make_float2(o1[d][2] * i11 - o2[d][2] * i21,
                                o1[d][3] * i11 - o2[d][3] * i21);
        *(float2*)(g_y + r0) = v0;
        *(float2*)(g_y + r1) = v1;
    }
}

// -------- GroupNorm per (b,h) over (T,HD); emits bf16 hi/lo split directly -
__global__ void groupnorm_kernel(const float* __restrict__ gn_w,
                                 const float* __restrict__ gn_b,
                                 __nv_bfloat16* __restrict__ AH,
                                 __nv_bfloat16* __restrict__ AL)
{
    __shared__ float rs[256], rq[256];
    const int bh = blockIdx.x;
    const float* src = g_y + (size_t)bh * TT * HD;
    const int tid = threadIdx.x;
    float s = 0.f, sq = 0.f;
    for (int i = tid; i < TT * HD; i += 256) {
        float v = src[i]; s += v; sq += v * v;
    }
    rs[tid] = s; rq[tid] = sq;
    __syncthreads();
    for (int off = 128; off > 0; off >>= 1) {
        if (tid < off) { rs[tid] += rs[tid + off]; rq[tid] += rq[tid + off]; }
        __syncthreads();
    }
    float mu  = rs[0] * (1.f / 65536.f);
    float var = rq[0] * (1.f / 65536.f) - mu * mu;
    float inv = rsqrtf(var + 1e-5f);
    int b = bh >> 4, h = bh & 15;
    for (int i = tid; i < TT * HD; i += 256) {
        int t = i >> 6, d = i & 63;
        float v = (src[i] - mu) * inv * gn_w[h * 64 + d] + gn_b[h * 64 + d];
        size_t o = (size_t)(b * TT + t) * DD + h * 64 + d;
        __nv_bfloat16 hi = __float2bfloat16(v);
        AH[o] = hi;
        AL[o] = __float2bfloat16(v - __bfloat162float(hi));
    }
}

// ---------------------------------------------------------------------------
extern "C" void kernel_launch(void* const* d_in, const int* in_sizes, int n_in,
                              void* d_out, int out_size)
{
    const float* x_q  = (const float*)d_in[0];
    const float* x_kv = (const float*)d_in[1];
    const float* Wq   = (const float*)d_in[2];
    const float* Wkv  = (const float*)d_in[3];
    const float* Wc   = (const float*)d_in[4];
    const float* qn1  = (const float*)d_in[5];
    const float* kn1  = (const float*)d_in[6];
    const float* qn2  = (const float*)d_in[7];
    const float* kn2  = (const float*)d_in[8];
    const float* gn_w = (const float*)d_in[9];
    const float* gn_b = (const float*)d_in[10];
    const float* lmb  = (const float*)d_in[11];
    float* out = (float*)d_out;
    (void)in_sizes; (void)n_in; (void)out_size;

    float *QQ, *KV;
    __nv_bfloat16 *AH, *AL, *BH, *BL;
    cudaGetSymbolAddress((void**)&QQ, g_QQ);
    cudaGetSymbolAddress((void**)&KV, g_KV);
    cudaGetSymbolAddress((void**)&AH, g_AH);
    cudaGetSymbolAddress((void**)&AL, g_AL);
    cudaGetSymbolAddress((void**)&BH, g_BH);
    cudaGetSymbolAddress((void**)&BL, g_BL);

    cudaFuncSetAttribute(mma_gemm,
        cudaFuncAttributeMaxDynamicSharedMemorySize, MG_TOTAL);
    cudaFuncSetAttribute(attn_mma,
        cudaFuncAttributeMaxDynamicSharedMemorySize, AT_SMEM);

    // 1) QQ = x_q @ Wq
    convA<<<4096, 256>>>(x_q, AH, AL);
    convBT<<<dim3(64, 32), dim3(32, 8)>>>(Wq, BH, BL, 1024, 2048);
    mma_gemm<<<dim3(16, 32), 256, MG_TOTAL>>>(AH, AL, BH, BL, QQ, 4096, 2048, 1024);
    // 2) KV = x_kv @ Wkv
    convA<<<4096, 256>>>(x_kv, AH, AL);
    convBT<<<dim3(96, 32), dim3(32, 8)>>>(Wkv, BH, BL, 1024, 3072);
    mma_gemm<<<dim3(24, 32), 256, MG_TOTAL>>>(AH, AL, BH, BL, KV, 4096, 3072, 1024);
    // 3) per-head RMSNorm -> bf16 hi/lo, head-major (Q pre-scaled)
    rms_q <<<16384, 256>>>(qn1, qn2);
    rms_kv<<<24576, 256>>>(kn1, kn2);
    // 4) tensor-core differential flash attention
    attn_mma<<<dim3(8, 16, 4), 256, AT_SMEM>>>(lmb);
    // 5) GroupNorm + relayout + bf16 split (fused)
    groupnorm_kernel<<<64, 256>>>(gn_w, gn_b, AH, AL);
    // 6) out = yt @ Wc
    convBT<<<dim3(32, 32), dim3(32, 8)>>>(Wc, BH, BL, 1024, 1024);
    mma_gemm<<<dim3(8, 32), 256, MG_TOTAL>>>(AH, AL, BH, BL, out, 4096, 1024, 1024);
}

// round 12
// speedup vs baseline: 8.9019x; 1.0302x over previous
#include <cuda_runtime.h>
#include <cuda_bf16.h>
#include <math.h>
#include <stdint.h>

#define BB 4
#define TT 1024
#define DD 1024
#define HH 16
#define HD 64

// softmax scale folded into Q: log2(e)/8
#define QSCALE 0.18033688011112042f

typedef unsigned long long ull;

// ---------------- scratch (device globals; no allocation allowed) ----------
__device__ float g_y [BB*HH*TT*HD];    // attention out (B,H,T,64) fp32
// bf16 split operands for the projection GEMMs
__device__ __nv_bfloat16 g_AH[4096*1024];
__device__ __nv_bfloat16 g_AL[4096*1024];
__device__ __nv_bfloat16 g_BH[3072*1024];   // transposed: [N,K]
__device__ __nv_bfloat16 g_BL[3072*1024];
// bf16 hi/lo attention operands, (B,H,T,64)
#define AELE (BB*HH*TT*HD)
__device__ __nv_bfloat16 g_q1h[AELE], g_q1l[AELE], g_q2h[AELE], g_q2l[AELE];
__device__ __nv_bfloat16 g_k1h[AELE], g_k1l[AELE], g_k2h[AELE], g_k2l[AELE];
__device__ __nv_bfloat16 g_vh [AELE], g_vl [AELE];

// =================== small asm helpers =====================================
__device__ __forceinline__ uint32_t s2u(const void* p) {
    uint32_t a;
    asm("{ .reg .u64 t; cvta.to.shared.u64 t, %1; cvt.u32.u64 %0, t; }" : "=r"(a) : "l"(p));
    return a;
}
__device__ __forceinline__ void cpa16(uint32_t d, const void* s) {
    asm volatile("cp.async.cg.shared.global [%0], [%1], 16;" :: "r"(d), "l"(s));
}
__device__ __forceinline__ void ldsm4(uint32_t* r, uint32_t a) {
    asm volatile("ldmatrix.sync.aligned.m8n8.x4.shared.b16 {%0,%1,%2,%3}, [%4];"
                 : "=r"(r[0]), "=r"(r[1]), "=r"(r[2]), "=r"(r[3]) : "r"(a));
}
__device__ __forceinline__ void ldsm4t(uint32_t* r, uint32_t a) {
    asm volatile("ldmatrix.sync.aligned.m8n8.x4.trans.shared.b16 {%0,%1,%2,%3}, [%4];"
                 : "=r"(r[0]), "=r"(r[1]), "=r"(r[2]), "=r"(r[3]) : "r"(a));
}
#define MMA_BF16(d, a, b)                                                     \
    asm volatile("mma.sync.aligned.m16n8k16.row.col.f32.bf16.bf16.f32 "       \
        "{%0,%1,%2,%3}, {%4,%5,%6,%7}, {%8,%9}, {%0,%1,%2,%3};"               \
        : "+f"((d)[0]), "+f"((d)[1]), "+f"((d)[2]), "+f"((d)[3])              \
        : "r"((a)[0]), "r"((a)[1]), "r"((a)[2]), "r"((a)[3]),                 \
          "r"((b)[0]), "r"((b)[1]))
__device__ __forceinline__ uint32_t swz(uint32_t bo) {
    return bo ^ ((bo >> 3) & 0x70);
}
__device__ __forceinline__ uint32_t pkhi(float a, float b) {
    uint32_t d;
    asm("prmt.b32 %0, %1, %2, 0x7632;" : "=r"(d)
        : "r"(__float_as_uint(a)), "r"(__float_as_uint(b)));
    return d;
}
__device__ __forceinline__ uint32_t pkbf2(float lo, float hi) {
    uint32_t d;
    asm("cvt.rn.bf16x2.f32 %0, %1, %2;" : "=r"(d) : "f"(hi), "f"(lo));
    return d;
}
__device__ __forceinline__ float trunclo(float f) {
    return f - __uint_as_float(__float_as_uint(f) & 0xFFFF0000u);
}
__device__ __forceinline__ float ex2(float x) {
    float y;
    asm("ex2.approx.f32 %0, %1;" : "=f"(y) : "f"(x));
    return y;
}

// =================== fp32 -> bf16 hi/lo split kernels ======================
__global__ void convA(const float* __restrict__ X, __nv_bfloat16* __restrict__ H,
                      __nv_bfloat16* __restrict__ L)
{
    int i = (blockIdx.x * 256 + threadIdx.x) * 4;
    float4 v = *(const float4*)(X + i);
    __nv_bfloat16 h0 = __float2bfloat16(v.x), h1 = __float2bfloat16(v.y);
    __nv_bfloat16 h2 = __float2bfloat16(v.z), h3 = __float2bfloat16(v.w);
    __nv_bfloat16 l0 = __float2bfloat16(v.x - __bfloat162float(h0));
    __nv_bfloat16 l1 = __float2bfloat16(v.y - __bfloat162float(h1));
    __nv_bfloat16 l2 = __float2bfloat16(v.z - __bfloat162float(h2));
    __nv_bfloat16 l3 = __float2bfloat16(v.w - __bfloat162float(h3));
    *(__nv_bfloat162*)(H + i)     = __nv_bfloat162(h0, h1);
    *(__nv_bfloat162*)(H + i + 2) = __nv_bfloat162(h2, h3);
    *(__nv_bfloat162*)(L + i)     = __nv_bfloat162(l0, l1);
    *(__nv_bfloat162*)(L + i + 2) = __nv_bfloat162(l2, l3);
}

__global__ void convBT(const float* __restrict__ W, __nv_bfloat16* __restrict__ H,
                       __nv_bfloat16* __restrict__ L, int K, int N)
{
    __shared__ float s[32][33];
    int nb = blockIdx.x * 32, kb = blockIdx.y * 32;
    int tx = threadIdx.x, ty = threadIdx.y;
#pragma unroll
    for (int i = 0; i < 4; i++)
        s[ty + i * 8][tx] = W[(size_t)(kb + ty + i * 8) * N + nb + tx];
    __syncthreads();
#pragma unroll
    for (int i = 0; i < 4; i++) {
        float v = s[tx][ty + i * 8];
        __nv_bfloat16 h = __float2bfloat16(v);
        __nv_bfloat16 l = __float2bfloat16(v - __bfloat162float(h));
        size_t o = (size_t)(nb + ty + i * 8) * K + kb + tx;
        H[o] = h; L[o] = l;
    }
}

// ============ bf16 split GEMM on mma.sync, templated epilogue ==============
// MODE 0: plain fp32 C store.
// MODE 1: fused per-head RMSNorm (x QSCALE) -> g_q{1,2}{h,l} head-major bf16.
// MODE 2: fused per-head RMSNorm -> g_k{1,2}{h,l}; part 2 = V copy -> g_v{h,l}.
#define MG_STAGE 65536
#define MG_TOTAL (2 * MG_STAGE)

template<int MODE>
__global__ __launch_bounds__(256, 1)
void mma_gemm(const __nv_bfloat16* __restrict__ Ah, const __nv_bfloat16* __restrict__ Al,
              const __nv_bfloat16* __restrict__ Bh, const __nv_bfloat16* __restrict__ Bl,
              float* __restrict__ C, const float* __restrict__ w1,
              const float* __restrict__ w2, int M, int N, int K)
{
    extern __shared__ char smem[];
    const uint32_t sb = s2u(smem);
    const int tid = threadIdx.x;
    const int wid = tid >> 5, lane = tid & 31;
    const int bx = blockIdx.x, by = blockIdx.y;
    const int wm = (wid & 3) * 32;
    const int wn = (wid >> 2) * 64;

    const __nv_bfloat16* pAh = Ah + (size_t)(by * 128) * K;
    const __nv_bfloat16* pAl = Al + (size_t)(by * 128) * K;
    const __nv_bfloat16* pBh = Bh + (size_t)(bx * 128) * K;
    const __nv_bfloat16* pBl = Bl + (size_t)(bx * 128) * K;

    const int NC = K >> 6;

    float acc[2][8][4];
#pragma unroll
    for (int mf = 0; mf < 2; mf++)
#pragma unroll
        for (int nf = 0; nf < 8; nf++)
#pragma unroll
            for (int q = 0; q < 4; q++) acc[mf][nf][q] = 0.f;

    auto issue = [&](int ch, int st) {
        uint32_t stb = sb + st * MG_STAGE;
        int k0 = ch << 6;
#pragma unroll
        for (int it = 0; it < 4; it++) {
            int idx = tid + it * 256;
            int row = idx >> 3, c8 = idx & 7;
            uint32_t so = swz(row * 128 + c8 * 16);
            size_t go = (size_t)row * K + k0 + c8 * 8;
            cpa16(stb + 0 * 16384 + so, pAh + go);
            cpa16(stb + 1 * 16384 + so, pAl + go);
            cpa16(stb + 2 * 16384 + so, pBh + go);
            cpa16(stb + 3 * 16384 + so, pBl + go);
        }
        asm volatile("cp.async.commit_group;" ::: "memory");
    };

    issue(0, 0);

    const int a_r  = lane & 15;
    const int a_kb = (lane >> 4) * 16;
    const int b_r  = (lane & 7) + ((lane >> 4) & 1) * 8;
    const int b_kb = ((lane >> 3) & 1) * 16;

    for (int ch = 0; ch < NC; ch++) {
        const int st = ch & 1;
        if (ch + 1 < NC) issue(ch + 1, st ^ 1);
        if (ch + 1 < NC)
            asm volatile("cp.async.wait_group 1;" ::: "memory");
        else
            asm volatile("cp.async.wait_group 0;" ::: "memory");
        __syncthreads();

        const uint32_t sAh = sb + st * MG_STAGE + 0 * 16384;
        const uint32_t sAl = sb + st * MG_STAGE + 1 * 16384;
        const uint32_t sBh = sb + st * MG_STAGE + 2 * 16384;
        const uint32_t sBl = sb + st * MG_STAGE + 3 * 16384;

#pragma unroll
        for (int ks = 0; ks < 4; ks++) {
            uint32_t aH[2][4], aL[2][4], bH[16], bL[16];
#pragma unroll
            for (int mf = 0; mf < 2; mf++) {
                uint32_t off = swz((wm + mf * 16 + a_r) * 128 + ks * 32 + a_kb);
                ldsm4(aH[mf], sAh + off);
                ldsm4(aL[mf], sAl + off);
            }
#pragma unroll
            for (int g = 0; g < 4; g++) {
                uint32_t off = swz((wn + g * 16 + b_r) * 128 + ks * 32 + b_kb);
                ldsm4(bH + g * 4, sBh + off);
                ldsm4(bL + g * 4, sBl + off);
            }
#pragma unroll
            for (int mf = 0; mf < 2; mf++)
#pragma unroll
                for (int nf = 0; nf < 8; nf++) {
                    MMA_BF16(acc[mf][nf], aH[mf], bH + nf * 2);
                    MMA_BF16(acc[mf][nf], aH[mf], bL + nf * 2);
                    MMA_BF16(acc[mf][nf], aL[mf], bH + nf * 2);
                }
        }
        __syncthreads();
    }

    const int er = lane >> 2, ec = (lane & 3) * 2;

    if (MODE == 0) {
#pragma unroll
        for (int mf = 0; mf < 2; mf++) {
#pragma unroll
            for (int nf = 0; nf < 8; nf++) {
                int row0 = by * 128 + wm + mf * 16 + er;
                int col  = bx * 128 + wn + nf * 8 + ec;
                float2 v0 = make_float2(acc[mf][nf][0], acc[mf][nf][1]);
                float2 v1 = make_float2(acc[mf][nf][2], acc[mf][nf][3]);
                *(float2*)(C + (size_t)row0 * N + col)       = v0;
                *(float2*)(C + (size_t)(row0 + 8) * N + col) = v1;
            }
        }
    } else {
        // ---- fused per-head RMSNorm epilogue ----
        const int gc   = bx * 128 + wn;        // 64-aligned global col base
        const int part = gc >> 10;             // MODE1: 0/1 (q1/q2); MODE2: 0/1/2
        const int hh   = (gc >> 6) & 15;
        const bool donorm = (MODE == 1) || (part < 2);
        const float* w = (part == 0) ? w1 : ((part == 1) ? w2 : (const float*)0);

        float wv[16];
        if (donorm) {
#pragma unroll
            for (int nf = 0; nf < 8; nf++) {
                wv[2 * nf]     = w[nf * 8 + ec];
                wv[2 * nf + 1] = w[nf * 8 + ec + 1];
            }
        }
        __nv_bfloat16 *dh, *dl;
        if (MODE == 1) { dh = part ? g_q2h : g_q1h; dl = part ? g_q2l : g_q1l; }
        else { dh = (part == 0) ? g_k1h : ((part == 1) ? g_k2h : g_vh);
               dl = (part == 0) ? g_k1l : ((part == 1) ? g_k2l : g_vl); }

#pragma unroll
        for (int mf = 0; mf < 2; mf++) {
            float s0 = 0.f, s1 = 0.f;
#pragma unroll
            for (int nf = 0; nf < 8; nf++) {
                s0 += acc[mf][nf][0] * acc[mf][nf][0] + acc[mf][nf][1] * acc[mf][nf][1];
                s1 += acc[mf][nf][2] * acc[mf][nf][2] + acc[mf][nf][3] * acc[mf][nf][3];
            }
            s0 += __shfl_xor_sync(0xffffffffu, s0, 1);
            s0 += __shfl_xor_sync(0xffffffffu, s0, 2);
            s1 += __shfl_xor_sync(0xffffffffu, s1, 1);
            s1 += __shfl_xor_sync(0xffffffffu, s1, 2);
            float in0 = 1.f, in1 = 1.f;
            if (donorm) {
                in0 = rsqrtf(s0 * (1.f / 64.f) + 1e-5f);
                in1 = rsqrtf(s1 * (1.f / 64.f) + 1e-5f);
                if (MODE == 1) { in0 *= QSCALE; in1 *= QSCALE; }
            }
            int r0 = by * 128 + wm + mf * 16 + er;
            int r1 = r0 + 8;
            size_t base0 = ((size_t)(((r0 >> 10) * 16 + hh) * 1024 + (r0 & 1023))) * 64;
            size_t base1 = ((size_t)(((r1 >> 10) * 16 + hh) * 1024 + (r1 & 1023))) * 64;
#pragma unroll
            for (int nf = 0; nf < 8; nf++) {
                int d = nf * 8 + ec;
                float v0 = acc[mf][nf][0] * in0, v1 = acc[mf][nf][1] * in0;
                float v2 = acc[mf][nf][2] * in1, v3 = acc[mf][nf][3] * in1;
                if (donorm) {
                    v0 *= wv[2 * nf]; v1 *= wv[2 * nf + 1];
                    v2 *= wv[2 * nf]; v3 *= wv[2 * nf + 1];
                }
                __nv_bfloat16 h0 = __float2bfloat16(v0), h1 = __float2bfloat16(v1);
                __nv_bfloat16 h2 = __float2bfloat16(v2), h3 = __float2bfloat16(v3);
                *(__nv_bfloat162*)(dh + base0 + d) = __nv_bfloat162(h0, h1);
                *(__nv_bfloat162*)(dh + base1 + d) = __nv_bfloat162(h2, h3);
                *(__nv_bfloat162*)(dl + base0 + d) = __nv_bfloat162(
                    __float2bfloat16(v0 - __bfloat162float(h0)),
                    __float2bfloat16(v1 - __bfloat162float(h1)));
                *(__nv_bfloat162*)(dl + base1 + d) = __nv_bfloat162(
                    __float2bfloat16(v2 - __bfloat162float(h2)),
                    __float2bfloat16(v3 - __bfloat162float(h3)));
            }
        }
    }
}

// ================= tensor-core differential flash attention ================
// CTA: 128 q-rows x one (b,h). 8 warps x 16 rows. KV chunks of 64 rows,
// double-buffered. No online max (|s/8| <= 8 bound); P = 2^(q·k·log2e/8).
// NOTE: trailing __syncthreads() in the chunk loop is LOAD-BEARING — it keeps
// the next iteration's cp.async prefetch from overwriting a stage other warps
// are still reading (post-timing divergence in R7 without it).
#define KVST 49152
#define AT_SMEM (4 * 16384 + 2 * KVST)

__global__ __launch_bounds__(256, 1)
void attn_mma(const float* __restrict__ lmb)
{
    extern __shared__ char smem[];
    const uint32_t sb = s2u(smem);
    const int tid = threadIdx.x;
    const int wid = tid >> 5, lane = tid & 31;
    const int qt = blockIdx.x, h = blockIdx.y, b = blockIdx.z;
    const size_t bh = (size_t)(b * HH + h) * (TT * HD);
    const int wm = wid * 16;
    const uint32_t kv0 = sb + 4 * 16384;

    // ---- Q tiles via cp.async ----
    {
        size_t qoff = bh + (size_t)qt * 128 * 64;
#pragma unroll
        for (int it = 0; it < 4; it++) {
            int idx = tid + it * 256;
            int row = idx >> 3, c8 = idx & 7;
            uint32_t so = swz(row * 128 + c8 * 16);
            size_t g = qoff + (size_t)row * 64 + c8 * 8;
            cpa16(sb + 0 * 16384 + so, g_q1h + g);
            cpa16(sb + 1 * 16384 + so, g_q1l + g);
            cpa16(sb + 2 * 16384 + so, g_q2h + g);
            cpa16(sb + 3 * 16384 + so, g_q2l + g);
        }
        asm volatile("cp.async.commit_group;" ::: "memory");
    }

    auto kvissue = [&](int kt, int st) {
        uint32_t stb = kv0 + st * KVST;
        size_t kbase = bh + (size_t)kt * 64 * 64;
#pragma unroll
        for (int it = 0; it < 2; it++) {
            int idx = tid + it * 256;
            int row = idx >> 3, c8 = idx & 7;
            uint32_t so = swz(row * 128 + c8 * 16);
            size_t g = kbase + (size_t)row * 64 + c8 * 8;
            cpa16(stb + 0 * 8192 + so, g_k1h + g);
            cpa16(stb + 1 * 8192 + so, g_k1l + g);
            cpa16(stb + 2 * 8192 + so, g_k2h + g);
            cpa16(stb + 3 * 8192 + so, g_k2l + g);
            cpa16(stb + 4 * 8192 + so, g_vh + g);
            cpa16(stb + 5 * 8192 + so, g_vl + g);
        }
        asm volatile("cp.async.commit_group;" ::: "memory");
    };

    kvissue(0, 0);

    float o1[8][4], o2[8][4];
#pragma unroll
    for (int d = 0; d < 8; d++)
#pragma unroll
        for (int q = 0; q < 4; q++) { o1[d][q] = 0.f; o2[d][q] = 0.f; }
    float l1[2] = {0.f, 0.f}, l2[2] = {0.f, 0.f};   // per-thread partials

    const uint32_t a_off = (wm + (lane & 15)) * 128 + (lane >> 4) * 16;
    const uint32_t b_off = ((lane & 7) + ((lane >> 4) & 1) * 8) * 128
                         + ((lane >> 3) & 1) * 16;
    const uint32_t v_off = (lane & 15) * 128 + (lane >> 4) * 16;

    for (int kt = 0; kt < 16; kt++) {
        const int st = kt & 1;
        if (kt + 1 < 16) kvissue(kt + 1, st ^ 1);
        if (kt + 1 < 16)
            asm volatile("cp.async.wait_group 1;" ::: "memory");
        else
            asm volatile("cp.async.wait_group 0;" ::: "memory");
        __syncthreads();

        const uint32_t stb = kv0 + st * KVST;

        uint32_t ph1[4][4], pl1[4][4], ph2[4][4], pl2[4][4];

#pragma unroll
        for (int br = 0; br < 2; br++) {
            const uint32_t sAh = sb + (br ? 2 : 0) * 16384;
            const uint32_t sAl = sAh + 16384;
            const uint32_t sBh = stb + (br ? 2 : 0) * 8192;
            const uint32_t sBl = sBh + 8192;
            float* l = br ? l2 : l1;

            // ---- S = Q K^T over 64 keys (3-product split) ----
            float sf[8][4];
#pragma unroll
            for (int nf = 0; nf < 8; nf++)
#pragma unroll
                for (int q = 0; q < 4; q++) sf[nf][q] = 0.f;
#pragma unroll
            for (int ks = 0; ks < 4; ks++) {
                uint32_t aH[4], aL[4];
                ldsm4(aH, sAh + swz(a_off + ks * 32));
                ldsm4(aL, sAl + swz(a_off + ks * 32));
#pragma unroll
                for (int g = 0; g < 4; g++) {
                    uint32_t bH[4], bL[4];
                    uint32_t off = swz(b_off + g * 2048 + ks * 32);
                    ldsm4(bH, sBh + off);
                    ldsm4(bL, sBl + off);
                    MMA_BF16(sf[2*g],   aH, bH);
                    MMA_BF16(sf[2*g],   aH, bL);
                    MMA_BF16(sf[2*g],   aL, bH);
                    MMA_BF16(sf[2*g+1], aH, bH + 2);
                    MMA_BF16(sf[2*g+1], aH, bL + 2);
                    MMA_BF16(sf[2*g+1], aL, bH + 2);
                }
            }

            // ---- P = 2^S ; accumulate per-thread l partials ----
            float p0 = 0.f, p1 = 0.f;
#pragma unroll
            for (int nf = 0; nf < 8; nf++) {
                sf[nf][0] = ex2(sf[nf][0]); p0 += sf[nf][0];
                sf[nf][1] = ex2(sf[nf][1]); p0 += sf[nf][1];
                sf[nf][2] = ex2(sf[nf][2]); p1 += sf[nf][2];
                sf[nf][3] = ex2(sf[nf][3]); p1 += sf[nf][3];
            }
            l[0] += p0; l[1] += p1;

            // ---- pack P fragments (bf16 hi/lo, A-layout) ----
            uint32_t (*ph)[4] = br ? ph2 : ph1;
            uint32_t (*pl)[4] = br ? pl2 : pl1;
#pragma unroll
            for (int kf = 0; kf < 4; kf++) {
                float* f0 = sf[2*kf];
                float* f1 = sf[2*kf+1];
                ph[kf][0] = pkhi(f0[0], f0[1]);
                ph[kf][1] = pkhi(f0[2], f0[3]);
                ph[kf][2] = pkhi(f1[0], f1[1]);
                ph[kf][3] = pkhi(f1[2], f1[3]);
                pl[kf][0] = pkbf2(trunclo(f0[0]), trunclo(f0[1]));
                pl[kf][1] = pkbf2(trunclo(f0[2]), trunclo(f0[3]));
                pl[kf][2] = pkbf2(trunclo(f1[0]), trunclo(f1[1]));
                pl[kf][3] = pkbf2(trunclo(f1[2]), trunclo(f1[3]));
            }
        }

        // ---- O += P V for both branches, V fragments loaded once ----
        const uint32_t sVh = stb + 4 * 8192;
        const uint32_t sVl = stb + 5 * 8192;
#pragma unroll
        for (int kf = 0; kf < 4; kf++) {
#pragma unroll
            for (int d2 = 0; d2 < 4; d2++) {
                uint32_t vH[4], vL[4];
                uint32_t off = swz(v_off + kf * 2048 + d2 * 32);
                ldsm4t(vH, sVh + off);
                ldsm4t(vL, sVl + off);
                MMA_BF16(o1[d2*2],   ph1[kf], vH);
                MMA_BF16(o1[d2*2],   ph1[kf], vL);
                MMA_BF16(o1[d2*2],   pl1[kf], vH);
                MMA_BF16(o1[d2*2+1], ph1[kf], vH + 2);
                MMA_BF16(o1[d2*2+1], ph1[kf], vL + 2);
                MMA_BF16(o1[d2*2+1], pl1[kf], vH + 2);
                MMA_BF16(o2[d2*2],   ph2[kf], vH);
                MMA_BF16(o2[d2*2],   ph2[kf], vL);
                MMA_BF16(o2[d2*2],   pl2[kf], vH);
                MMA_BF16(o2[d2*2+1], ph2[kf], vH + 2);
                MMA_BF16(o2[d2*2+1], ph2[kf], vL + 2);
                MMA_BF16(o2[d2*2+1], pl2[kf], vH + 2);
            }
        }

        __syncthreads();   // all warps done with stage st before it is refilled
    }

    // ---- reduce l across quads (columns of each row) ----
#pragma unroll
    for (int off = 1; off <= 2; off <<= 1) {
        l1[0] += __shfl_xor_sync(0xffffffffu, l1[0], off);
        l1[1] += __shfl_xor_sync(0xffffffffu, l1[1], off);
        l2[0] += __shfl_xor_sync(0xffffffffu, l2[0], off);
        l2[1] += __shfl_xor_sync(0xffffffffu, l2[1], off);
    }

    // ---- epilogue: y = O1/l1 - softplus(lmb)·O2/l2 ----
    float cH = log1pf(__expf(lmb[h]));
    float i10 = 1.f / l1[0], i11 = 1.f / l1[1];
    float i20 = cH / l2[0],  i21 = cH / l2[1];
    const int er = lane >> 2, ec = (lane & 3) * 2;
#pragma unroll
    for (int d = 0; d < 8; d++) {
        size_t r0 = bh + (size_t)(qt * 128 + wm + er) * 64 + d * 8 + ec;
        size_t r1 = r0 + 8 * 64;
        float2 v0 = make_float2(o1[d][0] * i10 - o2[d][0] * i20,
                                o1[d][1] * i10 - o2[d][1] * i20);
        float2 v1 = make_float2(o1[d][2] * i11 - o2[d][2] * i21,
                                o1[d][3] * i11 - o2[d][3] * i21);
        *(float2*)(g_y + r0) = v0;
        *(float2*)(g_y + r1) = v1;
    }
}

// -------- GroupNorm per (b,h) over (T,HD); emits bf16 hi/lo split directly -
__global__ void groupnorm_kernel(const float* __restrict__ gn_w,
                                 const float* __restrict__ gn_b,
                                 __nv_bfloat16* __restrict__ AH,
                                 __nv_bfloat16* __restrict__ AL)
{
    __shared__ float rs[256], rq[256];
    const int bh = blockIdx.x;
    const float* src = g_y + (size_t)bh * TT * HD;
    const int tid = threadIdx.x;
    float s = 0.f, sq = 0.f;
    for (int i = tid; i < TT * HD; i += 256) {
        float v = src[i]; s += v; sq += v * v;
    }
    rs[tid] = s; rq[tid] = sq;
    __syncthreads();
    for (int off = 128; off > 0; off >>= 1) {
        if (tid < off) { rs[tid] += rs[tid + off]; rq[tid] += rq[tid + off]; }
        __syncthreads();
    }
    float mu  = rs[0] * (1.f / 65536.f);
    float var = rq[0] * (1.f / 65536.f) - mu * mu;
    float inv = rsqrtf(var + 1e-5f);
    int b = bh >> 4, h = bh & 15;
    for (int i = tid; i < TT * HD; i += 256) {
        int t = i >> 6, d = i & 63;
        float v = (src[i] - mu) * inv * gn_w[h * 64 + d] + gn_b[h * 64 + d];
        size_t o = (size_t)(b * TT + t) * DD + h * 64 + d;
        __nv_bfloat16 hi = __float2bfloat16(v);
        AH[o] = hi;
        AL[o] = __float2bfloat16(v - __bfloat162float(hi));
    }
}

// ---------------------------------------------------------------------------
extern "C" void kernel_launch(void* const* d_in, const int* in_sizes, int n_in,
                              void* d_out, int out_size)
{
    const float* x_q  = (const float*)d_in[0];
    const float* x_kv = (const float*)d_in[1];
    const float* Wq   = (const float*)d_in[2];
    const float* Wkv  = (const float*)d_in[3];
    const float* Wc   = (const float*)d_in[4];
    const float* qn1  = (const float*)d_in[5];
    const float* kn1  = (const float*)d_in[6];
    const float* qn2  = (const float*)d_in[7];
    const float* kn2  = (const float*)d_in[8];
    const float* gn_w = (const float*)d_in[9];
    const float* gn_b = (const float*)d_in[10];
    const float* lmb  = (const float*)d_in[11];
    float* out = (float*)d_out;
    (void)in_sizes; (void)n_in; (void)out_size;

    __nv_bfloat16 *AH, *AL, *BH, *BL;
    cudaGetSymbolAddress((void**)&AH, g_AH);
    cudaGetSymbolAddress((void**)&AL, g_AL);
    cudaGetSymbolAddress((void**)&BH, g_BH);
    cudaGetSymbolAddress((void**)&BL, g_BL);

    cudaFuncSetAttribute(mma_gemm<0>,
        cudaFuncAttributeMaxDynamicSharedMemorySize, MG_TOTAL);
    cudaFuncSetAttribute(mma_gemm<1>,
        cudaFuncAttributeMaxDynamicSharedMemorySize, MG_TOTAL);
    cudaFuncSetAttribute(mma_gemm<2>,
        cudaFuncAttributeMaxDynamicSharedMemorySize, MG_TOTAL);
    cudaFuncSetAttribute(attn_mma,
        cudaFuncAttributeMaxDynamicSharedMemorySize, AT_SMEM);

    // 1) q projections + fused per-head RMSNorm -> bf16 hi/lo head-major
    convA<<<4096, 256>>>(x_q, AH, AL);
    convBT<<<dim3(64, 32), dim3(32, 8)>>>(Wq, BH, BL, 1024, 2048);
    mma_gemm<1><<<dim3(16, 32), 256, MG_TOTAL>>>(AH, AL, BH, BL,
        (float*)0, qn1, qn2, 4096, 2048, 1024);
    // 2) kv projections + fused RMSNorm / V split
    convA<<<4096, 256>>>(x_kv, AH, AL);
    convBT<<<dim3(96, 32), dim3(32, 8)>>>(Wkv, BH, BL, 1024, 3072);
    mma_gemm<2><<<dim3(24, 32), 256, MG_TOTAL>>>(AH, AL, BH, BL,
        (float*)0, kn1, kn2, 4096, 3072, 1024);
    // 3) tensor-core differential flash attention
    attn_mma<<<dim3(8, 16, 4), 256, AT_SMEM>>>(lmb);
    // 4) GroupNorm + relayout + bf16 split (fused)
    groupnorm_kernel<<<64, 256>>>(gn_w, gn_b, AH, AL);
    // 5) out = yt @ Wc
    convBT<<<dim3(32, 32), dim3(32, 8)>>>(Wc, BH, BL, 1024, 1024);
    mma_gemm<0><<<dim3(8, 32), 256, MG_TOTAL>>>(AH, AL, BH, BL,
        out, (float*)0, (float*)0, 4096, 1024, 1024);
}